// round 1
// baseline (speedup 1.0000x reference)
#include <cuda_runtime.h>
#include <cstdint>

#define BH        64
#define SEQ       1024
#define DH        64
#define ROWS      16
#define NTHREADS  256
#define PSTRIDE   1028
#define VSTRIDE   68
#define KTILE     128
#define NTILES    (SEQ / KTILE)

// smem pool byte offsets
#define OFF_P     0
#define SZ_P      (ROWS * PSTRIDE * 4)            // 65792
#define OFF_KV    (OFF_P + SZ_P)                   // 65792
#define SZ_KV     (KTILE * VSTRIDE * 4)            // 34816 (V tile; K tile 32768 fits)
#define OFF_Q2    (OFF_KV + SZ_KV)                 // 100608
#define SZ_Q2     (ROWS * DH * 8)                  // 8192  (Obuf aliases this in PV)
#define OFF_PADS  (OFF_Q2 + SZ_Q2)                 // 108800
#define SZ_PADS   (SEQ * 4)                        // 4096
#define OFF_L     (OFF_PADS + SZ_PADS)             // 112896
#define OFF_C     (OFF_L + ROWS * 4)               // 112960
#define SMEM_BYTES (OFF_C + ROWS * 4)              // 113024

// scratch: transposed K (16MB) + fallback output buffer (in case out_size
// covers only one of the two tuple outputs)
__device__ float g_kt[(size_t)BH * DH * SEQ];
__device__ float g_scratch[(size_t)BH * SEQ * SEQ];

// ---------------------------------------------------------------------------
// packed f32x2 helpers (sm_100+ PTX)
// ---------------------------------------------------------------------------
__device__ __forceinline__ void fma2(unsigned long long& acc,
                                     unsigned long long a, unsigned long long b) {
    asm("fma.rn.f32x2 %0, %1, %2, %0;" : "+l"(acc) : "l"(a), "l"(b));
}
__device__ __forceinline__ unsigned long long dup2(float x) {
    unsigned long long r;
    asm("mov.b64 %0, {%1, %1};" : "=l"(r) : "f"(x));
    return r;
}
__device__ __forceinline__ void unpk(unsigned long long v, float& lo, float& hi) {
    asm("mov.b64 {%0, %1}, %2;" : "=f"(lo), "=f"(hi) : "l"(v));
}

// ---------------------------------------------------------------------------
// Kernel 0: K [bh][s][d] -> g_kt [bh][d][s]   (coalesced tiled transpose)
// ---------------------------------------------------------------------------
__global__ void transpose_k_kernel(const float* __restrict__ k) {
    __shared__ float tile[32][33];
    const int bh = blockIdx.z;
    const int d0 = blockIdx.x * 32;
    const int s0 = blockIdx.y * 32;
    const float* kin  = k    + (size_t)bh * SEQ * DH;
    float*       kout = g_kt + (size_t)bh * DH * SEQ;
    const int tx = threadIdx.x, ty = threadIdx.y;
#pragma unroll
    for (int j = 0; j < 32; j += 8)
        tile[ty + j][tx] = kin[(size_t)(s0 + ty + j) * DH + (d0 + tx)];
    __syncthreads();
#pragma unroll
    for (int j = 0; j < 32; j += 8)
        kout[(size_t)(d0 + ty + j) * SEQ + (s0 + tx)] = tile[tx][ty + j];
}

// ---------------------------------------------------------------------------
// Kernel 1: per CTA = (bh, 16 query rows). Phases:
//   QK^T (f32x2 FFMA) -> exp+mask -> P in smem, row sums
//   normalize (+degenerate-row fix) -> write weights to gmem
//   P·V (f32x2 FFMA) -> write context
// ---------------------------------------------------------------------------
__global__ __launch_bounds__(NTHREADS, 2)
void attn_kernel(const float* __restrict__ q, const float* __restrict__ v,
                 const int* __restrict__ pad,
                 float* __restrict__ ctx, float* __restrict__ wout) {
    extern __shared__ char pool[];
    float*              Psm  = (float*)(pool + OFF_P);
    float*              KV   = (float*)(pool + OFF_KV);
    unsigned long long* Q2   = (unsigned long long*)(pool + OFF_Q2);
    float*              Obuf = (float*)(pool + OFF_Q2);   // alias: Q dead in PV
    int*                pads = (int*)(pool + OFF_PADS);
    float*              Lrow = (float*)(pool + OFF_L);
    float*              Crow = (float*)(pool + OFF_C);

    const int tid   = threadIdx.x;
    const int bh    = blockIdx.y;
    const int qbase = blockIdx.x * ROWS;
    const int b     = bh >> 4;

    // ---- prologue loads: Q (duplicated f32 pairs), pad row --------------
    const float* qg = q + ((size_t)bh * SEQ + qbase) * DH;
    for (int i = tid; i < ROWS * DH; i += NTHREADS) Q2[i] = dup2(qg[i]);
    const int* pg = pad + b * SEQ;
    for (int i = tid; i < SEQ; i += NTHREADS) pads[i] = pg[i];

    const int r    = tid >> 4;      // 0..15 query row in tile
    const int cg   = tid & 15;      // 0..15 group of 8 keys
    const int qrow = qbase + r;

    float lsum = 0.f, scnt = 0.f;
    const float* ktg = g_kt + (size_t)bh * DH * SEQ;

    // ---- phase 1: scores + exp into P smem -------------------------------
    for (int t = 0; t < NTILES; ++t) {
        __syncthreads();   // KV reuse fence (also orders Q2/pads on t==0)
        const float* src = ktg + t * KTILE;
#pragma unroll
        for (int i = 0; i < 8; ++i) {
            int idx = tid + i * NTHREADS;
            int row = idx >> 5, c4 = (idx & 31) << 2;
            *(float4*)&KV[row * KTILE + c4] =
                *(const float4*)&src[(size_t)row * SEQ + c4];
        }
        __syncthreads();

        unsigned long long a01 = 0, a23 = 0, a45 = 0, a67 = 0;
        const unsigned long long* q2r = Q2 + r * DH;
        const float* ks = KV + cg * 8;
#pragma unroll 16
        for (int d = 0; d < DH; ++d) {
            unsigned long long qq = q2r[d];
            const ulonglong2* kp = (const ulonglong2*)(ks + d * KTILE);
            ulonglong2 kA = kp[0];
            ulonglong2 kB = kp[1];
            fma2(a01, qq, kA.x); fma2(a23, qq, kA.y);
            fma2(a45, qq, kB.x); fma2(a67, qq, kB.y);
        }
        float sc[8];
        unpk(a01, sc[0], sc[1]); unpk(a23, sc[2], sc[3]);
        unpk(a45, sc[4], sc[5]); unpk(a67, sc[6], sc[7]);

        const int key0 = t * KTILE + cg * 8;
        float p[8];
#pragma unroll
        for (int i = 0; i < 8; ++i) {
            int key     = key0 + i;
            bool pd     = (pads[key] != 0);
            bool masked = pd || (key > qrow);
            float e     = masked ? 0.f : __expf(sc[i] * 0.125f);
            p[i] = e;
            lsum += e;
            bool singly = (key <= qrow) ? pd : !pd;   // degenerate-row support
            scnt += singly ? 1.f : 0.f;
        }
        float* pw = Psm + r * PSTRIDE + key0;
        *(float4*)pw       = make_float4(p[0], p[1], p[2], p[3]);
        *(float4*)(pw + 4) = make_float4(p[4], p[5], p[6], p[7]);
    }

    // ---- row reductions (16 lanes per row, within half-warp) -------------
#pragma unroll
    for (int o = 8; o > 0; o >>= 1) {
        lsum += __shfl_xor_sync(0xffffffffu, lsum, o);
        scnt += __shfl_xor_sync(0xffffffffu, scnt, o);
    }
    if (cg == 0) { Lrow[r] = lsum; Crow[r] = scnt; }
    __syncthreads();

    // ---- phase 2: normalize (+degenerate fix), write weights -------------
    {
        const float l     = Lrow[r];
        const bool  degen = (l == 0.f);           // all keys <= qrow padded
        const float inv   = 1.f / l;              // unused when degen
        const float fill  = 1.f / Crow[r];        // unused when !degen
        float* wrow = wout + ((size_t)bh * SEQ + qrow) * SEQ;
#pragma unroll
        for (int t = 0; t < NTILES; ++t) {
            const int key0 = t * KTILE + cg * 8;
            float* pw = Psm + r * PSTRIDE + key0;
            float4 A = *(float4*)pw;
            float4 Bv = *(float4*)(pw + 4);
            float w[8] = {A.x, A.y, A.z, A.w, Bv.x, Bv.y, Bv.z, Bv.w};
#pragma unroll
            for (int i = 0; i < 8; ++i) {
                int key = key0 + i;
                if (degen) {
                    bool pd     = (pads[key] != 0);
                    bool singly = (key <= qrow) ? pd : !pd;
                    w[i] = singly ? fill : 0.f;
                } else {
                    w[i] *= inv;
                }
            }
            float4 O1 = make_float4(w[0], w[1], w[2], w[3]);
            float4 O2 = make_float4(w[4], w[5], w[6], w[7]);
            *(float4*)pw         = O1;   // normalized P for the PV phase
            *(float4*)(pw + 4)   = O2;
            *(float4*)&wrow[key0]     = O1;
            *(float4*)&wrow[key0 + 4] = O2;
        }
    }
    __syncthreads();

    // ---- phase 3: context = P · V  ---------------------------------------
    const int r2  = tid >> 4;        // query row
    const int kh  = (tid >> 3) & 1;  // key-half within tile
    const int cg2 = tid & 7;         // group of 8 output dims
    unsigned long long o01 = 0, o23 = 0, o45 = 0, o67 = 0;
    const float* vg = v + (size_t)bh * SEQ * DH;

    for (int t = 0; t < NTILES; ++t) {
        __syncthreads();   // KV reuse fence
#pragma unroll
        for (int i = 0; i < 8; ++i) {
            int idx = tid + i * NTHREADS;
            int key = idx >> 4, d4 = (idx & 15) << 2;
            *(float4*)&KV[key * VSTRIDE + d4] =
                *(const float4*)&vg[(size_t)(t * KTILE + key) * DH + d4];
        }
        __syncthreads();

        const float* prow = Psm + r2 * PSTRIDE + t * KTILE + kh * 64;
        const float* vs   = KV + (kh * 64) * VSTRIDE + cg2 * 8;
#pragma unroll 16
        for (int k2 = 0; k2 < 64; ++k2) {
            unsigned long long pp = dup2(prow[k2]);
            const ulonglong2* vp = (const ulonglong2*)(vs + k2 * VSTRIDE);
            ulonglong2 vA = vp[0];
            ulonglong2 vB = vp[1];
            fma2(o01, pp, vA.x); fma2(o23, pp, vA.y);
            fma2(o45, pp, vB.x); fma2(o67, pp, vB.y);
        }
    }
    __syncthreads();       // KV & P done; Obuf (aliasing Q2) now safe to write

    float oo[8];
    unpk(o01, oo[0], oo[1]); unpk(o23, oo[2], oo[3]);
    unpk(o45, oo[4], oo[5]); unpk(o67, oo[6], oo[7]);
    float* ob = Obuf + r2 * DH + cg2 * 8;
    if (kh == 0) {
        *(float4*)ob       = make_float4(oo[0], oo[1], oo[2], oo[3]);
        *(float4*)(ob + 4) = make_float4(oo[4], oo[5], oo[6], oo[7]);
    }
    __syncthreads();
    if (kh == 1) {
        float4 A = *(float4*)ob, Bv = *(float4*)(ob + 4);
        A.x += oo[0]; A.y += oo[1]; A.z += oo[2]; A.w += oo[3];
        Bv.x += oo[4]; Bv.y += oo[5]; Bv.z += oo[6]; Bv.w += oo[7];
        *(float4*)ob = A; *(float4*)(ob + 4) = Bv;
    }
    __syncthreads();

    float* cgout = ctx + ((size_t)bh * SEQ + qbase) * DH;
    ((float4*)cgout)[tid] = ((const float4*)Obuf)[tid];   // 256 * float4 = 1024
}

// ---------------------------------------------------------------------------
extern "C" void kernel_launch(void* const* d_in, const int* in_sizes, int n_in,
                              void* d_out, int out_size) {
    (void)in_sizes; (void)n_in;
    const float* q   = (const float*)d_in[0];
    const float* k   = (const float*)d_in[1];
    const float* v   = (const float*)d_in[2];
    const int*   pad = (const int*)d_in[3];
    // d_in[4] (look_ahead_mask) is a deterministic triu — recomputed in-kernel.

    const long long CTXN = (long long)BH * SEQ * DH;    //  4,194,304
    const long long WN   = (long long)BH * SEQ * SEQ;   // 67,108,864

    float* ctxp;
    float* wp;
    if ((long long)out_size >= CTXN + WN) {
        ctxp = (float*)d_out;
        wp   = (float*)d_out + CTXN;
    } else if ((long long)out_size == WN) {
        void* s = nullptr;
        cudaGetSymbolAddress(&s, g_scratch);
        ctxp = (float*)s;
        wp   = (float*)d_out;
    } else {  // context only
        void* s = nullptr;
        cudaGetSymbolAddress(&s, g_scratch);
        ctxp = (float*)d_out;
        wp   = (float*)s;
    }

    static bool attr_done = false;
    if (!attr_done) {
        cudaFuncSetAttribute(attn_kernel,
                             cudaFuncAttributeMaxDynamicSharedMemorySize,
                             SMEM_BYTES);
        attr_done = true;
    }

    dim3 gt(DH / 32, SEQ / 32, BH), bt(32, 8);
    transpose_k_kernel<<<gt, bt>>>(k);

    dim3 ga(SEQ / ROWS, BH), ba(NTHREADS);
    attn_kernel<<<ga, ba, SMEM_BYTES>>>(q, v, pad, ctxp, wp);
}

// round 2
// speedup vs baseline: 3.1339x; 3.1339x over previous
#include <cuda_runtime.h>
#include <cuda_bf16.h>
#include <cstdint>

#define BH        64
#define SEQ       1024
#define DH        64
#define ROWS      16
#define NTHREADS  256
#define KTILE     128
#define NTILES    8
#define PSTRIDE   1028      // floats, %32==4 -> conflict-free frag reads
#define KSTRIDE   72        // bf16 elems per key row (144 B)
#define VSTRIDE   136       // bf16 elems per d row of transposed V (272 B)

// smem byte offsets
#define OFF_P    0
#define SZ_P     (ROWS * PSTRIDE * 4)            // 65792
#define OFF_KH   (OFF_P + SZ_P)                  // 65792
#define SZ_KH    (KTILE * KSTRIDE * 2)           // 18432
#define OFF_KL   (OFF_KH + SZ_KH)                // 84224
#define OFF_VH   OFF_KH                          // V aliases K (phases disjoint)
#define OFF_VL   (OFF_KH + DH * VSTRIDE * 2)     // 83200
#define OFF_QH   (OFF_KL + SZ_KH)                // 102656
#define SZ_QH    (ROWS * KSTRIDE * 2)            // 2304
#define OFF_QL   (OFF_QH + SZ_QH)                // 104960
#define OFF_PAD  (OFF_QL + SZ_QH)                // 107264
#define OFF_L    (OFF_PAD + SEQ * 4)             // 111360
#define OFF_C    (OFF_L + ROWS * 4)              // 111424
#define OFF_FLG  (OFF_C + ROWS * 4)              // 111488
#define SMEM_BYTES (OFF_FLG + 16)                // 111504  (x2 CTA = 223008 <= 227KB)

__device__ float g_scratch[(size_t)BH * SEQ * SEQ];  // fallback if out_size is partial

// ---------------------------------------------------------------------------
__device__ __forceinline__ uint32_t packsplit(float x, float y, uint32_t& lo) {
    __nv_bfloat16 hx = __float2bfloat16_rn(x);
    __nv_bfloat16 hy = __float2bfloat16_rn(y);
    __nv_bfloat16 lx = __float2bfloat16_rn(x - __bfloat162float(hx));
    __nv_bfloat16 ly = __float2bfloat16_rn(y - __bfloat162float(hy));
    lo = (uint32_t)__bfloat16_as_ushort(lx) | ((uint32_t)__bfloat16_as_ushort(ly) << 16);
    return (uint32_t)__bfloat16_as_ushort(hx) | ((uint32_t)__bfloat16_as_ushort(hy) << 16);
}

__device__ __forceinline__ void mma16816(float* c, const uint32_t* a,
                                         uint32_t b0, uint32_t b1) {
    asm volatile(
        "mma.sync.aligned.m16n8k16.row.col.f32.bf16.bf16.f32 "
        "{%0,%1,%2,%3},{%4,%5,%6,%7},{%8,%9},{%0,%1,%2,%3};"
        : "+f"(c[0]), "+f"(c[1]), "+f"(c[2]), "+f"(c[3])
        : "r"(a[0]), "r"(a[1]), "r"(a[2]), "r"(a[3]), "r"(b0), "r"(b1));
}

__device__ __forceinline__ float epival(float s, int col, int qrow, const int* pads) {
    bool m = (pads[col] != 0) || (col > qrow);
    return m ? 0.f : __expf(s * 0.125f);
}

// ---------------------------------------------------------------------------
__global__ __launch_bounds__(NTHREADS, 2)
void attn_mma_kernel(const float* __restrict__ q, const float* __restrict__ k,
                     const float* __restrict__ v, const int* __restrict__ pad,
                     float* __restrict__ ctx, float* __restrict__ wout) {
    extern __shared__ char pool[];
    float* Psm  = (float*)(pool + OFF_P);
    int*   pads = (int*)(pool + OFF_PAD);
    float* Lrow = (float*)(pool + OFF_L);
    float* Crow = (float*)(pool + OFF_C);
    int*   flg  = (int*)(pool + OFF_FLG);

    const int tid  = threadIdx.x;
    const int wid  = tid >> 5;
    const int lane = tid & 31;
    const int r    = lane >> 2;     // fragment row group
    const int tg   = lane & 3;      // thread-in-group
    const int bh   = blockIdx.y;
    const int qb   = blockIdx.x;
    const int qbase = qb * ROWS;
    const int b    = bh >> 4;

    // ---- phase 0: zero P/Lrow/flag, load pads, load+split Q --------------
    {
        float4 z = make_float4(0.f, 0.f, 0.f, 0.f);
        float4* p4 = (float4*)Psm;
        for (int i = tid; i < ROWS * PSTRIDE / 4; i += NTHREADS) p4[i] = z;
        if (tid < ROWS) Lrow[tid] = 0.f;
        if (tid == 0) flg[0] = 0;
        const int* pg = pad + b * SEQ;
        for (int i = tid; i < SEQ; i += NTHREADS) pads[i] = pg[i];

        const float* qg = q + ((size_t)bh * SEQ + qbase) * DH;
        int row = tid >> 4, d4 = (tid & 15) * 4;          // 256 threads cover 16x16
        float4 f = *(const float4*)&qg[row * DH + d4];
        uint32_t l0, l1;
        uint32_t h0 = packsplit(f.x, f.y, l0);
        uint32_t h1 = packsplit(f.z, f.w, l1);
        *(uint2*)(pool + OFF_QH + row * 144 + d4 * 2) = make_uint2(h0, h1);
        *(uint2*)(pool + OFF_QL + row * 144 + d4 * 2) = make_uint2(l0, l1);
    }
    __syncthreads();

    // ---- load Q a-fragments once into registers --------------------------
    uint32_t qa_h[4][4], qa_l[4][4];
#pragma unroll
    for (int ks = 0; ks < 4; ++ks) {
        int c2 = tg * 2 + ks * 16;                        // d index
        qa_h[ks][0] = *(uint32_t*)(pool + OFF_QH + (r)     * 144 + c2 * 2);
        qa_h[ks][1] = *(uint32_t*)(pool + OFF_QH + (r + 8) * 144 + c2 * 2);
        qa_h[ks][2] = *(uint32_t*)(pool + OFF_QH + (r)     * 144 + (c2 + 8) * 2);
        qa_h[ks][3] = *(uint32_t*)(pool + OFF_QH + (r + 8) * 144 + (c2 + 8) * 2);
        qa_l[ks][0] = *(uint32_t*)(pool + OFF_QL + (r)     * 144 + c2 * 2);
        qa_l[ks][1] = *(uint32_t*)(pool + OFF_QL + (r + 8) * 144 + c2 * 2);
        qa_l[ks][2] = *(uint32_t*)(pool + OFF_QL + (r)     * 144 + (c2 + 8) * 2);
        qa_l[ks][3] = *(uint32_t*)(pool + OFF_QL + (r + 8) * 144 + (c2 + 8) * 2);
    }

    // ---- phase 1: QK^T + exp into Psm (causal tile skip) ------------------
    const int qk_tiles = (qbase + ROWS - 1) / KTILE + 1;
    const int n0 = wid * 16;                              // warp's 16 cols in tile
    const int qrow0 = qbase + r, qrow1 = qbase + r + 8;
    float lsum0 = 0.f, lsum1 = 0.f;

    for (int t = 0; t < qk_tiles; ++t) {
        __syncthreads();
        const float* kg = k + ((size_t)bh * SEQ + t * KTILE) * DH;
#pragma unroll
        for (int i = 0; i < 8; ++i) {                     // 2048 float4 / 256 thr
            int idx = tid + i * NTHREADS;
            int row = idx >> 4, d4 = (idx & 15) * 4;
            float4 f = *(const float4*)&kg[row * DH + d4];
            uint32_t l0, l1;
            uint32_t h0 = packsplit(f.x, f.y, l0);
            uint32_t h1 = packsplit(f.z, f.w, l1);
            *(uint2*)(pool + OFF_KH + row * 144 + d4 * 2) = make_uint2(h0, h1);
            *(uint2*)(pool + OFF_KL + row * 144 + d4 * 2) = make_uint2(l0, l1);
        }
        __syncthreads();

        float c0[4] = {0, 0, 0, 0}, c1[4] = {0, 0, 0, 0};
#pragma unroll
        for (int ks = 0; ks < 4; ++ks) {
            int dlo = (tg * 2 + ks * 16) * 2;             // byte offset of k-low pair
            int key0 = n0 + r;                            // b-frag n = lane>>2
#pragma unroll
            for (int nt = 0; nt < 2; ++nt) {
                int kb = (key0 + nt * 8) * 144;
                uint32_t bh0 = *(uint32_t*)(pool + OFF_KH + kb + dlo);
                uint32_t bh1 = *(uint32_t*)(pool + OFF_KH + kb + dlo + 16);
                uint32_t bl0 = *(uint32_t*)(pool + OFF_KL + kb + dlo);
                uint32_t bl1 = *(uint32_t*)(pool + OFF_KL + kb + dlo + 16);
                float* cc = nt ? c1 : c0;
                mma16816(cc, qa_h[ks], bh0, bh1);
                mma16816(cc, qa_h[ks], bl0, bl1);
                mma16816(cc, qa_l[ks], bh0, bh1);
            }
        }

        // epilogue: scale, mask, exp, store, row-sum accumulate
        int colb = t * KTILE + n0 + tg * 2;
#pragma unroll
        for (int nt = 0; nt < 2; ++nt) {
            float* cc = nt ? c1 : c0;
            int cb = colb + nt * 8;
            float e0 = epival(cc[0], cb,     qrow0, pads);
            float e1 = epival(cc[1], cb + 1, qrow0, pads);
            float e2 = epival(cc[2], cb,     qrow1, pads);
            float e3 = epival(cc[3], cb + 1, qrow1, pads);
            Psm[r * PSTRIDE + cb]           = e0;
            Psm[r * PSTRIDE + cb + 1]       = e1;
            Psm[(r + 8) * PSTRIDE + cb]     = e2;
            Psm[(r + 8) * PSTRIDE + cb + 1] = e3;
            lsum0 += e0 + e1;
            lsum1 += e2 + e3;
        }
    }

    lsum0 += __shfl_xor_sync(0xffffffffu, lsum0, 1);
    lsum0 += __shfl_xor_sync(0xffffffffu, lsum0, 2);
    lsum1 += __shfl_xor_sync(0xffffffffu, lsum1, 1);
    lsum1 += __shfl_xor_sync(0xffffffffu, lsum1, 2);
    if (tg == 0) {
        atomicAdd(&Lrow[r], lsum0);
        atomicAdd(&Lrow[r + 8], lsum1);
    }
    __syncthreads();

    // ---- phase 2a: Crow (degenerate fill count) + degen flag --------------
    {
        int row = tid >> 4, ch = tid & 15;
        int qrow = qbase + row;
        int cnt = 0;
        for (int kx = ch * 64; kx < ch * 64 + 64; ++kx) {
            bool pd = pads[kx] != 0;
            cnt += ((kx <= qrow) ? pd : !pd) ? 1 : 0;
        }
        cnt += __shfl_xor_sync(0xffffffffu, cnt, 1);
        cnt += __shfl_xor_sync(0xffffffffu, cnt, 2);
        cnt += __shfl_xor_sync(0xffffffffu, cnt, 4);
        cnt += __shfl_xor_sync(0xffffffffu, cnt, 8);
        if (ch == 0) {
            Crow[row] = (float)cnt;
            if (Lrow[row] == 0.f) flg[0] = 1;
        }
    }
    __syncthreads();

    // ---- phase 2b: normalize (+degenerate fill), write W gmem + Psm ------
    {
        int row = tid >> 4, j = tid & 15;
        int qrow = qbase + row;
        float l = Lrow[row];
        bool degen = (l == 0.f);
        float inv  = 1.f / l;
        float fill = 1.f / Crow[row];
        float* prow = Psm + row * PSTRIDE;
        float* wrow = wout + ((size_t)bh * SEQ + qrow) * SEQ;
#pragma unroll
        for (int i = 0; i < 16; ++i) {
            int col = (j + i * 16) * 4;
            float4 pv = *(float4*)&prow[col];
            float w[4] = {pv.x, pv.y, pv.z, pv.w};
#pragma unroll
            for (int u = 0; u < 4; ++u) {
                int kx = col + u;
                if (degen) {
                    bool pd = pads[kx] != 0;
                    w[u] = ((kx <= qrow) ? pd : !pd) ? fill : 0.f;
                } else {
                    w[u] *= inv;
                }
            }
            float4 o = make_float4(w[0], w[1], w[2], w[3]);
            *(float4*)&prow[col] = o;
            *(float4*)&wrow[col] = o;
        }
    }
    __syncthreads();
    const int pv_tiles = flg[0] ? NTILES : qk_tiles;

    // ---- phase 3: ctx = W · V ---------------------------------------------
    float oc[4] = {0, 0, 0, 0};
    const int dg = wid * 8 + r;                           // b-frag d column

    for (int t = 0; t < pv_tiles; ++t) {
        __syncthreads();
        const float* vg = v + ((size_t)bh * SEQ + t * KTILE) * DH;
#pragma unroll
        for (int i = 0; i < 8; ++i) {                     // load + transpose-split V
            int idx = tid + i * NTHREADS;
            int key = idx >> 4, d4 = (idx & 15) * 4;
            float4 f = *(const float4*)&vg[key * DH + d4];
            float vv[4] = {f.x, f.y, f.z, f.w};
#pragma unroll
            for (int u = 0; u < 4; ++u) {
                __nv_bfloat16 h = __float2bfloat16_rn(vv[u]);
                __nv_bfloat16 lo = __float2bfloat16_rn(vv[u] - __bfloat162float(h));
                *(uint16_t*)(pool + OFF_VH + (d4 + u) * 272 + key * 2) = __bfloat16_as_ushort(h);
                *(uint16_t*)(pool + OFF_VL + (d4 + u) * 272 + key * 2) = __bfloat16_as_ushort(lo);
            }
        }
        __syncthreads();

#pragma unroll
        for (int ks = 0; ks < 8; ++ks) {
            int kc = t * KTILE + ks * 16 + tg * 2;        // key col for a-frag
            float2 p00 = *(float2*)&Psm[r * PSTRIDE + kc];
            float2 p10 = *(float2*)&Psm[(r + 8) * PSTRIDE + kc];
            float2 p01 = *(float2*)&Psm[r * PSTRIDE + kc + 8];
            float2 p11 = *(float2*)&Psm[(r + 8) * PSTRIDE + kc + 8];
            uint32_t ah[4], al[4];
            ah[0] = packsplit(p00.x, p00.y, al[0]);
            ah[1] = packsplit(p10.x, p10.y, al[1]);
            ah[2] = packsplit(p01.x, p01.y, al[2]);
            ah[3] = packsplit(p11.x, p11.y, al[3]);

            int keyl = (ks * 16 + tg * 2) * 2;            // byte offset within V row
            uint32_t bh0 = *(uint32_t*)(pool + OFF_VH + dg * 272 + keyl);
            uint32_t bh1 = *(uint32_t*)(pool + OFF_VH + dg * 272 + keyl + 16);
            uint32_t bl0 = *(uint32_t*)(pool + OFF_VL + dg * 272 + keyl);
            uint32_t bl1 = *(uint32_t*)(pool + OFF_VL + dg * 272 + keyl + 16);
            mma16816(oc, ah, bh0, bh1);
            mma16816(oc, ah, bl0, bl1);
            mma16816(oc, al, bh0, bh1);
        }
    }

    // ---- epilogue: write context ------------------------------------------
    {
        int d0 = wid * 8 + tg * 2;                        // C-frag col = lane%4 based
        float* crow = ctx + ((size_t)bh * SEQ + qbase) * DH;
        *(float2*)&crow[r * DH + d0]       = make_float2(oc[0], oc[1]);
        *(float2*)&crow[(r + 8) * DH + d0] = make_float2(oc[2], oc[3]);
    }
}

// ---------------------------------------------------------------------------
extern "C" void kernel_launch(void* const* d_in, const int* in_sizes, int n_in,
                              void* d_out, int out_size) {
    (void)in_sizes; (void)n_in;
    const float* q   = (const float*)d_in[0];
    const float* k   = (const float*)d_in[1];
    const float* v   = (const float*)d_in[2];
    const int*   pad = (const int*)d_in[3];
    // d_in[4] (look_ahead_mask) is deterministic triu — recomputed in-kernel.

    const long long CTXN = (long long)BH * SEQ * DH;    //  4,194,304
    const long long WN   = (long long)BH * SEQ * SEQ;   // 67,108,864

    float* ctxp;
    float* wp;
    if ((long long)out_size >= CTXN + WN) {
        ctxp = (float*)d_out;
        wp   = (float*)d_out + CTXN;
    } else if ((long long)out_size == WN) {
        void* s = nullptr;
        cudaGetSymbolAddress(&s, g_scratch);
        ctxp = (float*)s;
        wp   = (float*)d_out;
    } else {
        void* s = nullptr;
        cudaGetSymbolAddress(&s, g_scratch);
        ctxp = (float*)d_out;
        wp   = (float*)s;
    }

    static bool attr_done = false;
    if (!attr_done) {
        cudaFuncSetAttribute(attn_mma_kernel,
                             cudaFuncAttributeMaxDynamicSharedMemorySize,
                             SMEM_BYTES);
        attr_done = true;
    }

    dim3 ga(SEQ / ROWS, BH), ba(NTHREADS);
    attn_mma_kernel<<<ga, ba, SMEM_BYTES>>>(q, k, v, pad, ctxp, wp);
}

// round 4
// speedup vs baseline: 5.1871x; 1.6552x over previous
#include <cuda_runtime.h>
#include <cuda_bf16.h>
#include <cstdint>

#define BH        64
#define SEQ       1024
#define DH        64
#define ROWS      16
#define NTHREADS  256
#define KTILE     128
#define NTILES    8
#define PSTRIDE   1028              // fp32 elems; row = 4112 B (≡16 mod 128)
#define PROWB     4112
#define KROWB     144               // K/Q smem row bytes (64 bf16 + pad)
#define VROWB     272               // V^T smem row bytes (128 bf16 + pad)

// smem byte offsets
#define OFF_P    0
#define SZ_P     (ROWS * PROWB)                  // 65792
#define OFF_KH   SZ_P                            // 65792
#define SZ_KH    (KTILE * KROWB)                 // 18432
#define OFF_KL   (OFF_KH + SZ_KH)                // 84224
#define OFF_VH   OFF_KH                          // V^T aliases K (phases disjoint)
#define SZ_VH    (DH * VROWB)                    // 17408
#define OFF_VL   (OFF_VH + SZ_VH)                // 83200
#define OFF_QH   (OFF_KL + SZ_KH)                // 102656
#define SZ_QH    (ROWS * KROWB)                  // 2304
#define OFF_QL   (OFF_QH + SZ_QH)                // 104960
#define OFF_PAD  (OFF_QL + SZ_QH)                // 107264
#define OFF_L    (OFF_PAD + SEQ * 4)             // 111360
#define OFF_C    (OFF_L + ROWS * 4)              // 111424
#define OFF_FLG  (OFF_C + ROWS * 4)              // 111488
#define SMEM_BYTES (OFF_FLG + 16)                // 111504 (×2 CTA ≤ 227KB)

// P bf16-split addressing: 16B slot per 4 cols = [hi0..3 | lo0..3]
#define PB(row, kk) ((row) * PROWB + (((kk) >> 2) << 4) + (((kk) & 3) << 1))

__device__ __nv_bfloat16 g_kh[(size_t)BH * SEQ * DH];
__device__ __nv_bfloat16 g_kl[(size_t)BH * SEQ * DH];
__device__ __nv_bfloat16 g_vth[(size_t)BH * DH * SEQ];   // V^T [bh][d][s]
__device__ __nv_bfloat16 g_vtl[(size_t)BH * DH * SEQ];
__device__ float g_scratch[(size_t)BH * SEQ * SEQ];

// ---------------------------------------------------------------------------
__device__ __forceinline__ uint32_t packsplit(float x, float y, uint32_t& lo) {
    __nv_bfloat16 hx = __float2bfloat16_rn(x);
    __nv_bfloat16 hy = __float2bfloat16_rn(y);
    __nv_bfloat16 lx = __float2bfloat16_rn(x - __bfloat162float(hx));
    __nv_bfloat16 ly = __float2bfloat16_rn(y - __bfloat162float(hy));
    lo = (uint32_t)__bfloat16_as_ushort(lx) | ((uint32_t)__bfloat16_as_ushort(ly) << 16);
    return (uint32_t)__bfloat16_as_ushort(hx) | ((uint32_t)__bfloat16_as_ushort(hy) << 16);
}

__device__ __forceinline__ void mma16816(float* c, const uint32_t* a,
                                         uint32_t b0, uint32_t b1) {
    asm volatile(
        "mma.sync.aligned.m16n8k16.row.col.f32.bf16.bf16.f32 "
        "{%0,%1,%2,%3},{%4,%5,%6,%7},{%8,%9},{%0,%1,%2,%3};"
        : "+f"(c[0]), "+f"(c[1]), "+f"(c[2]), "+f"(c[3])
        : "r"(a[0]), "r"(a[1]), "r"(a[2]), "r"(a[3]), "r"(b0), "r"(b1));
}

__device__ __forceinline__ void ldsm4(uint32_t* r, uint32_t addr) {
    asm volatile("ldmatrix.sync.aligned.m8n8.x4.shared.b16 {%0,%1,%2,%3},[%4];"
                 : "=r"(r[0]), "=r"(r[1]), "=r"(r[2]), "=r"(r[3]) : "r"(addr));
}
__device__ __forceinline__ void ldsm2(uint32_t& r0, uint32_t& r1, uint32_t addr) {
    asm volatile("ldmatrix.sync.aligned.m8n8.x2.shared.b16 {%0,%1},[%2];"
                 : "=r"(r0), "=r"(r1) : "r"(addr));
}

__device__ __forceinline__ float epival(float s, int col, int qrow, const int* pads) {
    bool m = (pads[col] != 0) || (col > qrow);
    return m ? 0.f : __expf(s * 0.125f);
}

// ---------------------------------------------------------------------------
// prep 1: K f32 -> bf16 hi/lo (same layout)
__global__ void split_k_kernel(const float* __restrict__ k) {
    int idx = blockIdx.x * 256 + threadIdx.x;            // over N/4 float4s
    float4 f = ((const float4*)k)[idx];
    uint32_t l0, l1;
    uint32_t h0 = packsplit(f.x, f.y, l0);
    uint32_t h1 = packsplit(f.z, f.w, l1);
    ((uint2*)g_kh)[idx] = make_uint2(h0, h1);
    ((uint2*)g_kl)[idx] = make_uint2(l0, l1);
}

// prep 2: V f32 [bh][s][d] -> V^T bf16 hi/lo [bh][d][s]
__global__ void vt_split_kernel(const float* __restrict__ v) {
    __shared__ float tile[32][33];
    const int bh = blockIdx.z;
    const int d0 = blockIdx.x * 32;
    const int s0 = blockIdx.y * 32;
    const float* vin = v + (size_t)bh * SEQ * DH;
    const int tx = threadIdx.x, ty = threadIdx.y;
#pragma unroll
    for (int j = 0; j < 32; j += 8)
        tile[ty + j][tx] = vin[(size_t)(s0 + ty + j) * DH + (d0 + tx)];
    __syncthreads();
#pragma unroll
    for (int j = 0; j < 32; j += 8) {
        float x = tile[tx][ty + j];
        __nv_bfloat16 h = __float2bfloat16_rn(x);
        __nv_bfloat16 l = __float2bfloat16_rn(x - __bfloat162float(h));
        size_t o = (size_t)(bh * DH + d0 + ty + j) * SEQ + s0 + tx;
        g_vth[o] = h;
        g_vtl[o] = l;
    }
}

// ---------------------------------------------------------------------------
__global__ __launch_bounds__(NTHREADS, 2)
void attn_mma_kernel(const float* __restrict__ q, const int* __restrict__ pad,
                     float* __restrict__ ctx, float* __restrict__ wout) {
    extern __shared__ char pool[];
    float* Psm  = (float*)(pool + OFF_P);
    int*   pads = (int*)(pool + OFF_PAD);
    float* Lrow = (float*)(pool + OFF_L);
    float* Crow = (float*)(pool + OFF_C);
    int*   flg  = (int*)(pool + OFF_FLG);
    const uint32_t smem0 = (uint32_t)__cvta_generic_to_shared(pool);

    const int tid  = threadIdx.x;
    const int wid  = tid >> 5;
    const int lane = tid & 31;
    const int r    = lane >> 2;
    const int tg   = lane & 3;
    const int bh   = blockIdx.y;
    const int qbase = blockIdx.x * ROWS;
    const int b    = bh >> 4;

    // ---- phase 0 ----------------------------------------------------------
    {
        float4 z = make_float4(0.f, 0.f, 0.f, 0.f);
        float4* p4 = (float4*)Psm;
        for (int i = tid; i < ROWS * PSTRIDE / 4; i += NTHREADS) p4[i] = z;
        if (tid < ROWS) Lrow[tid] = 0.f;
        if (tid == 0) flg[0] = 0;
        const int* pg = pad + b * SEQ;
        for (int i = tid; i < SEQ; i += NTHREADS) pads[i] = pg[i];

        // load + split Q (16x64, once per CTA)
        const float* qg = q + ((size_t)bh * SEQ + qbase) * DH;
        int row = tid >> 4, d4 = (tid & 15) * 4;
        float4 f = *(const float4*)&qg[row * DH + d4];
        uint32_t l0, l1;
        uint32_t h0 = packsplit(f.x, f.y, l0);
        uint32_t h1 = packsplit(f.z, f.w, l1);
        *(uint2*)(pool + OFF_QH + row * KROWB + d4 * 2) = make_uint2(h0, h1);
        *(uint2*)(pool + OFF_QL + row * KROWB + d4 * 2) = make_uint2(l0, l1);
    }

    // LDSM lane address bases
    const uint32_t qA = smem0 + OFF_QH +
        ((lane & 7) + ((lane >> 3) & 1) * 8) * KROWB + ((lane >> 4) & 1) * 16;
    const int n0 = wid * 16;
    const uint32_t kA = smem0 + OFF_KH +
        (n0 + (lane & 7) + ((lane >> 4) & 1) * 8) * KROWB + ((lane >> 3) & 1) * 16;
    const int d0 = wid * 8;
    const uint32_t vA = smem0 + OFF_VH +
        (d0 + (lane & 7)) * VROWB + ((lane >> 3) & 1) * 16;

    // ---- phase 1: QK^T + exp ----------------------------------------------
    const int qk_tiles = (qbase + ROWS - 1) / KTILE + 1;
    const int qrow0 = qbase + r, qrow1 = qbase + r + 8;
    float lsum0 = 0.f, lsum1 = 0.f;

    for (int t = 0; t < qk_tiles; ++t) {
        __syncthreads();
        const uint4* sh = (const uint4*)(g_kh + ((size_t)bh * SEQ + t * KTILE) * DH);
        const uint4* sl = (const uint4*)(g_kl + ((size_t)bh * SEQ + t * KTILE) * DH);
#pragma unroll
        for (int i = 0; i < 4; ++i) {                    // 1024 uint4 per buffer
            int idx = tid + i * NTHREADS;
            int row = idx >> 3, seg = idx & 7;
            *(uint4*)(pool + OFF_KH + row * KROWB + seg * 16) = sh[idx];
            *(uint4*)(pool + OFF_KL + row * KROWB + seg * 16) = sl[idx];
        }
        __syncthreads();

        float c0[4] = {0, 0, 0, 0}, c1[4] = {0, 0, 0, 0};
#pragma unroll
        for (int ks = 0; ks < 4; ++ks) {
            uint32_t qh[4], ql[4], kh[4], kl[4];
            ldsm4(qh, qA + ks * 32);
            ldsm4(ql, qA + ks * 32 + SZ_QH);
            ldsm4(kh, kA + ks * 32);
            ldsm4(kl, kA + ks * 32 + SZ_KH);
            mma16816(c0, qh, kh[0], kh[1]);
            mma16816(c0, qh, kl[0], kl[1]);
            mma16816(c0, ql, kh[0], kh[1]);
            mma16816(c1, qh, kh[2], kh[3]);
            mma16816(c1, qh, kl[2], kl[3]);
            mma16816(c1, ql, kh[2], kh[3]);
        }

        int colb = t * KTILE + n0 + tg * 2;
#pragma unroll
        for (int nt = 0; nt < 2; ++nt) {
            float* cc = nt ? c1 : c0;
            int cb = colb + nt * 8;
            float e0 = epival(cc[0], cb,     qrow0, pads);
            float e1 = epival(cc[1], cb + 1, qrow0, pads);
            float e2 = epival(cc[2], cb,     qrow1, pads);
            float e3 = epival(cc[3], cb + 1, qrow1, pads);
            *(float2*)&Psm[r * PSTRIDE + cb]       = make_float2(e0, e1);
            *(float2*)&Psm[(r + 8) * PSTRIDE + cb] = make_float2(e2, e3);
            lsum0 += e0 + e1;
            lsum1 += e2 + e3;
        }
    }

    lsum0 += __shfl_xor_sync(0xffffffffu, lsum0, 1);
    lsum0 += __shfl_xor_sync(0xffffffffu, lsum0, 2);
    lsum1 += __shfl_xor_sync(0xffffffffu, lsum1, 1);
    lsum1 += __shfl_xor_sync(0xffffffffu, lsum1, 2);
    if (tg == 0) {
        atomicAdd(&Lrow[r], lsum0);
        atomicAdd(&Lrow[r + 8], lsum1);
    }
    __syncthreads();

    // ---- phase 2a: degenerate detection -----------------------------------
    {
        int row = tid >> 4, ch = tid & 15;
        int qrow = qbase + row;
        int cnt = 0;
        for (int kx = ch * 64; kx < ch * 64 + 64; ++kx) {
            bool pd = pads[kx] != 0;
            cnt += ((kx <= qrow) ? pd : !pd) ? 1 : 0;
        }
        cnt += __shfl_xor_sync(0xffffffffu, cnt, 1);
        cnt += __shfl_xor_sync(0xffffffffu, cnt, 2);
        cnt += __shfl_xor_sync(0xffffffffu, cnt, 4);
        cnt += __shfl_xor_sync(0xffffffffu, cnt, 8);
        if (ch == 0) {
            Crow[row] = (float)cnt;
            if (Lrow[row] == 0.f) flg[0] = 1;
        }
    }
    __syncthreads();

    // ---- phase 2b: normalize, write W, in-place bf16 split of P -----------
    {
        int row = tid >> 4, j = tid & 15;
        int qrow = qbase + row;
        float l = Lrow[row];
        bool degen = (l == 0.f);
        float inv  = 1.f / l;
        float fill = 1.f / Crow[row];
        float* prow = Psm + row * PSTRIDE;
        float* wrow = wout + ((size_t)bh * SEQ + qrow) * SEQ;
#pragma unroll
        for (int i = 0; i < 16; ++i) {
            int col = (j + i * 16) * 4;
            float4 pv = *(float4*)&prow[col];
            float w[4] = {pv.x, pv.y, pv.z, pv.w};
#pragma unroll
            for (int u = 0; u < 4; ++u) {
                int kx = col + u;
                if (degen) {
                    bool pd = pads[kx] != 0;
                    w[u] = ((kx <= qrow) ? pd : !pd) ? fill : 0.f;
                } else {
                    w[u] *= inv;
                }
            }
            *(float4*)&wrow[col] = make_float4(w[0], w[1], w[2], w[3]);
            uint32_t l01, l23;
            uint32_t h01 = packsplit(w[0], w[1], l01);
            uint32_t h23 = packsplit(w[2], w[3], l23);
            *(uint4*)&prow[col] = make_uint4(h01, h23, l01, l23);  // same 16B slot
        }
    }
    __syncthreads();
    const int pv_tiles = flg[0] ? NTILES : qk_tiles;

    // ---- phase 3: ctx = W · V ----------------------------------------------
    float oc[4] = {0, 0, 0, 0};
    for (int t = 0; t < pv_tiles; ++t) {
        __syncthreads();
        const __nv_bfloat16* vhb = g_vth + (size_t)bh * DH * SEQ + t * KTILE;
        const __nv_bfloat16* vlb = g_vtl + (size_t)bh * DH * SEQ + t * KTILE;
#pragma unroll
        for (int i = 0; i < 4; ++i) {                    // 1024 uint4 per buffer
            int idx = tid + i * NTHREADS;
            int d = idx >> 4, seg = idx & 15;
            *(uint4*)(pool + OFF_VH + d * VROWB + seg * 16) =
                *(const uint4*)(vhb + (size_t)d * SEQ + seg * 8);
            *(uint4*)(pool + OFF_VL + d * VROWB + seg * 16) =
                *(const uint4*)(vlb + (size_t)d * SEQ + seg * 8);
        }
        __syncthreads();

#pragma unroll
        for (int ks = 0; ks < 8; ++ks) {
            int kc = t * KTILE + ks * 16 + tg * 2;       // FIX: include t*KTILE
            uint32_t ah[4], al[4];
            ah[0] = *(uint32_t*)(pool + PB(r,     kc));
            ah[1] = *(uint32_t*)(pool + PB(r + 8, kc));
            ah[2] = *(uint32_t*)(pool + PB(r,     kc + 8));
            ah[3] = *(uint32_t*)(pool + PB(r + 8, kc + 8));
            al[0] = *(uint32_t*)(pool + PB(r,     kc)     + 8);
            al[1] = *(uint32_t*)(pool + PB(r + 8, kc)     + 8);
            al[2] = *(uint32_t*)(pool + PB(r,     kc + 8) + 8);
            al[3] = *(uint32_t*)(pool + PB(r + 8, kc + 8) + 8);
            uint32_t bh0, bh1, bl0, bl1;
            ldsm2(bh0, bh1, vA + ks * 32);
            ldsm2(bl0, bl1, vA + ks * 32 + SZ_VH);
            mma16816(oc, ah, bh0, bh1);
            mma16816(oc, ah, bl0, bl1);
            mma16816(oc, al, bh0, bh1);
        }
    }

    // ---- epilogue: context --------------------------------------------------
    {
        int dc = wid * 8 + tg * 2;
        float* crow = ctx + ((size_t)bh * SEQ + qbase) * DH;
        *(float2*)&crow[r * DH + dc]       = make_float2(oc[0], oc[1]);
        *(float2*)&crow[(r + 8) * DH + dc] = make_float2(oc[2], oc[3]);
    }
}

// ---------------------------------------------------------------------------
extern "C" void kernel_launch(void* const* d_in, const int* in_sizes, int n_in,
                              void* d_out, int out_size) {
    (void)in_sizes; (void)n_in;
    const float* q   = (const float*)d_in[0];
    const float* k   = (const float*)d_in[1];
    const float* v   = (const float*)d_in[2];
    const int*   pad = (const int*)d_in[3];

    const long long CTXN = (long long)BH * SEQ * DH;
    const long long WN   = (long long)BH * SEQ * SEQ;

    float* ctxp;
    float* wp;
    if ((long long)out_size >= CTXN + WN) {
        ctxp = (float*)d_out;
        wp   = (float*)d_out + CTXN;
    } else if ((long long)out_size == WN) {
        void* s = nullptr;
        cudaGetSymbolAddress(&s, g_scratch);
        ctxp = (float*)s;
        wp   = (float*)d_out;
    } else {
        void* s = nullptr;
        cudaGetSymbolAddress(&s, g_scratch);
        ctxp = (float*)d_out;
        wp   = (float*)s;
    }

    static bool attr_done = false;
    if (!attr_done) {
        cudaFuncSetAttribute(attn_mma_kernel,
                             cudaFuncAttributeMaxDynamicSharedMemorySize,
                             SMEM_BYTES);
        attr_done = true;
    }

    split_k_kernel<<<(BH * SEQ * DH / 4 + 255) / 256, 256>>>(k);
    dim3 gt(DH / 32, SEQ / 32, BH), bt(32, 8);
    vt_split_kernel<<<gt, bt>>>(v);

    dim3 ga(SEQ / ROWS, BH), ba(NTHREADS);
    attn_mma_kernel<<<ga, ba, SMEM_BYTES>>>(q, pad, ctxp, wp);
}

// round 5
// speedup vs baseline: 5.6757x; 1.0942x over previous
#include <cuda_runtime.h>
#include <cuda_bf16.h>
#include <cstdint>

#define BH        64
#define SEQ       1024
#define DH        64
#define ROWS      32
#define NTHREADS  512
#define KTILE     128
#define NTILES    8
#define PSTRIDE   1028              // fp32 elems; row = 4112 B
#define PROWB     4112
#define KROWB     144               // K/Q smem row bytes (64 bf16 + pad)
#define VROWB     272               // V^T smem row bytes (128 bf16 + pad)
#define SZ_KH     18432             // 128*144 (one K sub-buffer)
#define SZ_VH     17408             // 64*272  (one V sub-buffer)
#define KBUF      36864             // hi+lo per K/V stage buffer

// smem byte offsets
#define OFF_P    0
#define SZ_P     (ROWS * PROWB)                  // 131584
#define OFF_K0   SZ_P                            // 131584
#define OFF_K1   (OFF_K0 + KBUF)                 // 168448
#define OFF_QH   (OFF_K1 + KBUF)                 // 205312
#define SZ_QROW  (ROWS * KROWB)                  // 4608
#define OFF_QL   (OFF_QH + SZ_QROW)              // 209920
#define OFF_PAD  (OFF_QL + SZ_QROW)              // 214528
#define OFF_L    (OFF_PAD + SEQ * 4)             // 218624
#define OFF_C    (OFF_L + ROWS * 4)              // 218752
#define OFF_FLG  (OFF_C + ROWS * 4)              // 218880
#define SMEM_BYTES (OFF_FLG + 16)                // 218896 (< 227KB optin)

// P bf16-split addressing: 16B slot per 4 cols = [hi0..3 | lo0..3]
#define PB(row, kk) ((row) * PROWB + (((kk) >> 2) << 4) + (((kk) & 3) << 1))

#define CP_COMMIT() asm volatile("cp.async.commit_group;")
#define CP_WAIT(n)  asm volatile("cp.async.wait_group %0;" :: "n"(n))

__device__ __nv_bfloat16 g_kh[(size_t)BH * SEQ * DH];
__device__ __nv_bfloat16 g_kl[(size_t)BH * SEQ * DH];
__device__ __nv_bfloat16 g_vth[(size_t)BH * DH * SEQ];   // V^T [bh][d][s]
__device__ __nv_bfloat16 g_vtl[(size_t)BH * DH * SEQ];
__device__ float g_scratch[(size_t)BH * SEQ * SEQ];

// ---------------------------------------------------------------------------
__device__ __forceinline__ uint32_t packsplit(float x, float y, uint32_t& lo) {
    __nv_bfloat16 hx = __float2bfloat16_rn(x);
    __nv_bfloat16 hy = __float2bfloat16_rn(y);
    __nv_bfloat16 lx = __float2bfloat16_rn(x - __bfloat162float(hx));
    __nv_bfloat16 ly = __float2bfloat16_rn(y - __bfloat162float(hy));
    lo = (uint32_t)__bfloat16_as_ushort(lx) | ((uint32_t)__bfloat16_as_ushort(ly) << 16);
    return (uint32_t)__bfloat16_as_ushort(hx) | ((uint32_t)__bfloat16_as_ushort(hy) << 16);
}

__device__ __forceinline__ void mma16816(float* c, const uint32_t* a,
                                         uint32_t b0, uint32_t b1) {
    asm volatile(
        "mma.sync.aligned.m16n8k16.row.col.f32.bf16.bf16.f32 "
        "{%0,%1,%2,%3},{%4,%5,%6,%7},{%8,%9},{%0,%1,%2,%3};"
        : "+f"(c[0]), "+f"(c[1]), "+f"(c[2]), "+f"(c[3])
        : "r"(a[0]), "r"(a[1]), "r"(a[2]), "r"(a[3]), "r"(b0), "r"(b1));
}

__device__ __forceinline__ void ldsm4(uint32_t* r, uint32_t addr) {
    asm volatile("ldmatrix.sync.aligned.m8n8.x4.shared.b16 {%0,%1,%2,%3},[%4];"
                 : "=r"(r[0]), "=r"(r[1]), "=r"(r[2]), "=r"(r[3]) : "r"(addr));
}
__device__ __forceinline__ void ldsm2(uint32_t& r0, uint32_t& r1, uint32_t addr) {
    asm volatile("ldmatrix.sync.aligned.m8n8.x2.shared.b16 {%0,%1},[%2];"
                 : "=r"(r0), "=r"(r1) : "r"(addr));
}

__device__ __forceinline__ float epival(float s, int col, int qrow, const int* pads) {
    bool m = (pads[col] != 0) || (col > qrow);
    return m ? 0.f : __expf(s * 0.125f);
}

__device__ __forceinline__ void stcs4(float* p, float4 v) {
    asm volatile("st.global.cs.v4.f32 [%0],{%1,%2,%3,%4};"
                 :: "l"(p), "f"(v.x), "f"(v.y), "f"(v.z), "f"(v.w));
}

// ---- cp.async tile fills ----------------------------------------------------
__device__ __forceinline__ void fill_k_tile(uint32_t sb, const __nv_bfloat16* gh,
                                            const __nv_bfloat16* gl, int tid) {
#pragma unroll
    for (int i = 0; i < 2; ++i) {
        int c = tid + i * NTHREADS;                  // 0..1023
        int row = c >> 3, seg = c & 7;
        uint32_t so = sb + row * KROWB + seg * 16;
        asm volatile("cp.async.cg.shared.global [%0], [%1], 16;"
                     :: "r"(so), "l"(gh + row * DH + seg * 8));
        asm volatile("cp.async.cg.shared.global [%0], [%1], 16;"
                     :: "r"(so + SZ_KH), "l"(gl + row * DH + seg * 8));
    }
}
__device__ __forceinline__ void fill_v_tile(uint32_t sb, const __nv_bfloat16* gh,
                                            const __nv_bfloat16* gl, int tid) {
#pragma unroll
    for (int i = 0; i < 2; ++i) {
        int c = tid + i * NTHREADS;                  // 0..1023
        int row = c >> 4, seg = c & 15;
        uint32_t so = sb + row * VROWB + seg * 16;
        asm volatile("cp.async.cg.shared.global [%0], [%1], 16;"
                     :: "r"(so), "l"(gh + (size_t)row * SEQ + seg * 8));
        asm volatile("cp.async.cg.shared.global [%0], [%1], 16;"
                     :: "r"(so + SZ_VH), "l"(gl + (size_t)row * SEQ + seg * 8));
    }
}

// ---------------------------------------------------------------------------
// prep 1: K f32 -> bf16 hi/lo (same layout)
__global__ void split_k_kernel(const float* __restrict__ k) {
    int idx = blockIdx.x * 256 + threadIdx.x;
    float4 f = ((const float4*)k)[idx];
    uint32_t l0, l1;
    uint32_t h0 = packsplit(f.x, f.y, l0);
    uint32_t h1 = packsplit(f.z, f.w, l1);
    ((uint2*)g_kh)[idx] = make_uint2(h0, h1);
    ((uint2*)g_kl)[idx] = make_uint2(l0, l1);
}

// prep 2: V f32 [bh][s][d] -> V^T bf16 hi/lo [bh][d][s]
__global__ void vt_split_kernel(const float* __restrict__ v) {
    __shared__ float tile[32][33];
    const int bh = blockIdx.z;
    const int d0 = blockIdx.x * 32;
    const int s0 = blockIdx.y * 32;
    const float* vin = v + (size_t)bh * SEQ * DH;
    const int tx = threadIdx.x, ty = threadIdx.y;
#pragma unroll
    for (int j = 0; j < 32; j += 8)
        tile[ty + j][tx] = vin[(size_t)(s0 + ty + j) * DH + (d0 + tx)];
    __syncthreads();
#pragma unroll
    for (int j = 0; j < 32; j += 8) {
        float x = tile[tx][ty + j];
        __nv_bfloat16 h = __float2bfloat16_rn(x);
        __nv_bfloat16 l = __float2bfloat16_rn(x - __bfloat162float(h));
        size_t o = (size_t)(bh * DH + d0 + ty + j) * SEQ + s0 + tx;
        g_vth[o] = h;
        g_vtl[o] = l;
    }
}

// ---------------------------------------------------------------------------
__global__ __launch_bounds__(NTHREADS, 1)
void attn_mma_kernel(const float* __restrict__ q, const int* __restrict__ pad,
                     float* __restrict__ ctx, float* __restrict__ wout) {
    extern __shared__ char pool[];
    float* Psm  = (float*)(pool + OFF_P);
    int*   pads = (int*)(pool + OFF_PAD);
    float* Lrow = (float*)(pool + OFF_L);
    float* Crow = (float*)(pool + OFF_C);
    int*   flg  = (int*)(pool + OFF_FLG);
    const uint32_t smem0 = (uint32_t)__cvta_generic_to_shared(pool);

    const int tid  = threadIdx.x;
    const int wid  = tid >> 5;
    const int lane = tid & 31;
    const int r    = lane >> 2;
    const int tg   = lane & 3;
    const int wq   = wid >> 3;          // row block 0/1
    const int wn   = wid & 7;           // col/dim block
    const int bh   = blockIdx.y;
    const int qbase = blockIdx.x * ROWS;
    const int b    = bh >> 4;

    const __nv_bfloat16* khb = g_kh + (size_t)bh * SEQ * DH;
    const __nv_bfloat16* klb = g_kl + (size_t)bh * SEQ * DH;
    const __nv_bfloat16* vhb = g_vth + (size_t)bh * DH * SEQ;
    const __nv_bfloat16* vlb = g_vtl + (size_t)bh * DH * SEQ;

    const int qk_tiles = (qbase + ROWS - 1) / KTILE + 1;

    // prefetch K tile 0 immediately
    fill_k_tile(smem0 + OFF_K0, khb, klb, tid);
    CP_COMMIT();

    // ---- phase 0 ----------------------------------------------------------
    {
        float4 z = make_float4(0.f, 0.f, 0.f, 0.f);
        float4* p4 = (float4*)Psm;
        for (int i = tid; i < ROWS * PSTRIDE / 4; i += NTHREADS) p4[i] = z;
        if (tid < ROWS) Lrow[tid] = 0.f;
        if (tid == 0) flg[0] = 0;
        const int* pg = pad + b * SEQ;
        for (int i = tid; i < SEQ; i += NTHREADS) pads[i] = pg[i];

        // load + split Q (32x64, once per CTA)
        const float* qg = q + ((size_t)bh * SEQ + qbase) * DH;
        int row = tid >> 4, d4 = (tid & 15) * 4;
        float4 f = *(const float4*)&qg[row * DH + d4];
        uint32_t l0, l1;
        uint32_t h0 = packsplit(f.x, f.y, l0);
        uint32_t h1 = packsplit(f.z, f.w, l1);
        *(uint2*)(pool + OFF_QH + row * KROWB + d4 * 2) = make_uint2(h0, h1);
        *(uint2*)(pool + OFF_QL + row * KROWB + d4 * 2) = make_uint2(l0, l1);
    }
    __syncthreads();

    // ---- hoist Q a-fragments to registers ---------------------------------
    const uint32_t qA = smem0 + OFF_QH +
        (wq * 16 + (lane & 7) + ((lane >> 3) & 1) * 8) * KROWB + ((lane >> 4) & 1) * 16;
    uint32_t qa_h[4][4], qa_l[4][4];
#pragma unroll
    for (int ks = 0; ks < 4; ++ks) {
        ldsm4(qa_h[ks], qA + ks * 32);
        ldsm4(qa_l[ks], qA + ks * 32 + SZ_QROW);
    }

    // K/V LDSM relative lane addresses
    const int n0 = wn * 16;
    const uint32_t kRel =
        (n0 + (lane & 7) + ((lane >> 4) & 1) * 8) * KROWB + ((lane >> 3) & 1) * 16;
    const uint32_t vRel =
        (wn * 8 + (lane & 7)) * VROWB + ((lane >> 3) & 1) * 16;

    // ---- phase 1: QK^T + exp ----------------------------------------------
    const int pr0 = wq * 16 + r;
    const int qrow0 = qbase + pr0, qrow1 = qrow0 + 8;
    float lsum0 = 0.f, lsum1 = 0.f;

    for (int t = 0; t < qk_tiles; ++t) {
        const uint32_t kb = smem0 + ((t & 1) ? OFF_K1 : OFF_K0);
        if (t + 1 < qk_tiles) {
            fill_k_tile(smem0 + (((t + 1) & 1) ? OFF_K1 : OFF_K0),
                        khb + (t + 1) * KTILE * DH, klb + (t + 1) * KTILE * DH, tid);
            CP_COMMIT();
            CP_WAIT(1);
        } else {
            CP_WAIT(0);
        }
        __syncthreads();

        float c0[4] = {0, 0, 0, 0}, c1[4] = {0, 0, 0, 0};
#pragma unroll
        for (int ks = 0; ks < 4; ++ks) {
            uint32_t kh[4], kl[4];
            ldsm4(kh, kb + kRel + ks * 32);
            ldsm4(kl, kb + SZ_KH + kRel + ks * 32);
            mma16816(c0, qa_h[ks], kh[0], kh[1]);
            mma16816(c0, qa_h[ks], kl[0], kl[1]);
            mma16816(c0, qa_l[ks], kh[0], kh[1]);
            mma16816(c1, qa_h[ks], kh[2], kh[3]);
            mma16816(c1, qa_h[ks], kl[2], kl[3]);
            mma16816(c1, qa_l[ks], kh[2], kh[3]);
        }

        int colb = t * KTILE + n0 + tg * 2;
#pragma unroll
        for (int nt = 0; nt < 2; ++nt) {
            float* cc = nt ? c1 : c0;
            int cb = colb + nt * 8;
            float e0 = epival(cc[0], cb,     qrow0, pads);
            float e1 = epival(cc[1], cb + 1, qrow0, pads);
            float e2 = epival(cc[2], cb,     qrow1, pads);
            float e3 = epival(cc[3], cb + 1, qrow1, pads);
            *(float2*)&Psm[pr0 * PSTRIDE + cb]       = make_float2(e0, e1);
            *(float2*)&Psm[(pr0 + 8) * PSTRIDE + cb] = make_float2(e2, e3);
            lsum0 += e0 + e1;
            lsum1 += e2 + e3;
        }
        __syncthreads();
    }

    // prefetch V tile 0 (hides behind reductions + phase 2)
    fill_v_tile(smem0 + OFF_K0, vhb, vlb, tid);
    CP_COMMIT();

    lsum0 += __shfl_xor_sync(0xffffffffu, lsum0, 1);
    lsum0 += __shfl_xor_sync(0xffffffffu, lsum0, 2);
    lsum1 += __shfl_xor_sync(0xffffffffu, lsum1, 1);
    lsum1 += __shfl_xor_sync(0xffffffffu, lsum1, 2);
    if (tg == 0) {
        atomicAdd(&Lrow[pr0], lsum0);
        atomicAdd(&Lrow[pr0 + 8], lsum1);
    }
    __syncthreads();

    // ---- phase 2a: degenerate detection -----------------------------------
    {
        int row = tid >> 4, ch = tid & 15;
        int qrow = qbase + row;
        int cnt = 0;
        for (int kx = ch * 64; kx < ch * 64 + 64; ++kx) {
            bool pd = pads[kx] != 0;
            cnt += ((kx <= qrow) ? pd : !pd) ? 1 : 0;
        }
        cnt += __shfl_xor_sync(0xffffffffu, cnt, 1);
        cnt += __shfl_xor_sync(0xffffffffu, cnt, 2);
        cnt += __shfl_xor_sync(0xffffffffu, cnt, 4);
        cnt += __shfl_xor_sync(0xffffffffu, cnt, 8);
        if (ch == 0) {
            Crow[row] = (float)cnt;
            if (Lrow[row] == 0.f) flg[0] = 1;
        }
    }
    __syncthreads();

    // ---- phase 2b: normalize, write W (streaming), in-place bf16 split ----
    {
        int row = tid >> 4, j = tid & 15;
        int qrow = qbase + row;
        float l = Lrow[row];
        bool degen = (l == 0.f);
        float inv  = 1.f / l;
        float fill = 1.f / Crow[row];
        float* prow = Psm + row * PSTRIDE;
        float* wrow = wout + ((size_t)bh * SEQ + qrow) * SEQ;
#pragma unroll
        for (int i = 0; i < 16; ++i) {
            int col = (j + i * 16) * 4;
            float4 pv = *(float4*)&prow[col];
            float w[4] = {pv.x, pv.y, pv.z, pv.w};
#pragma unroll
            for (int u = 0; u < 4; ++u) {
                int kx = col + u;
                if (degen) {
                    bool pd = pads[kx] != 0;
                    w[u] = ((kx <= qrow) ? pd : !pd) ? fill : 0.f;
                } else {
                    w[u] *= inv;
                }
            }
            stcs4(&wrow[col], make_float4(w[0], w[1], w[2], w[3]));
            uint32_t l01, l23;
            uint32_t h01 = packsplit(w[0], w[1], l01);
            uint32_t h23 = packsplit(w[2], w[3], l23);
            *(uint4*)&prow[col] = make_uint4(h01, h23, l01, l23);
        }
    }
    __syncthreads();
    const int pv_tiles = flg[0] ? NTILES : qk_tiles;

    // ---- phase 3: ctx = W · V ----------------------------------------------
    float oc[4] = {0, 0, 0, 0};
    for (int t = 0; t < pv_tiles; ++t) {
        const uint32_t vb = smem0 + ((t & 1) ? OFF_K1 : OFF_K0);
        if (t + 1 < pv_tiles) {
            fill_v_tile(smem0 + (((t + 1) & 1) ? OFF_K1 : OFF_K0),
                        vhb + (t + 1) * KTILE, vlb + (t + 1) * KTILE, tid);
            CP_COMMIT();
            CP_WAIT(1);
        } else {
            CP_WAIT(0);
        }
        __syncthreads();

#pragma unroll
        for (int ks = 0; ks < 8; ++ks) {
            int kc = t * KTILE + ks * 16 + tg * 2;
            uint32_t ah[4], al[4];
            ah[0] = *(uint32_t*)(pool + PB(pr0,     kc));
            ah[1] = *(uint32_t*)(pool + PB(pr0 + 8, kc));
            ah[2] = *(uint32_t*)(pool + PB(pr0,     kc + 8));
            ah[3] = *(uint32_t*)(pool + PB(pr0 + 8, kc + 8));
            al[0] = *(uint32_t*)(pool + PB(pr0,     kc)     + 8);
            al[1] = *(uint32_t*)(pool + PB(pr0 + 8, kc)     + 8);
            al[2] = *(uint32_t*)(pool + PB(pr0,     kc + 8) + 8);
            al[3] = *(uint32_t*)(pool + PB(pr0 + 8, kc + 8) + 8);
            uint32_t bh0, bh1, bl0, bl1;
            ldsm2(bh0, bh1, vb + vRel + ks * 32);
            ldsm2(bl0, bl1, vb + SZ_VH + vRel + ks * 32);
            mma16816(oc, ah, bh0, bh1);
            mma16816(oc, ah, bl0, bl1);
            mma16816(oc, al, bh0, bh1);
        }
        __syncthreads();
    }

    // ---- epilogue: context --------------------------------------------------
    {
        int dc = wn * 8 + tg * 2;
        float* crow = ctx + ((size_t)bh * SEQ + qbase) * DH;
        *(float2*)&crow[pr0 * DH + dc]       = make_float2(oc[0], oc[1]);
        *(float2*)&crow[(pr0 + 8) * DH + dc] = make_float2(oc[2], oc[3]);
    }
}

// ---------------------------------------------------------------------------
extern "C" void kernel_launch(void* const* d_in, const int* in_sizes, int n_in,
                              void* d_out, int out_size) {
    (void)in_sizes; (void)n_in;
    const float* q   = (const float*)d_in[0];
    const float* k   = (const float*)d_in[1];
    const float* v   = (const float*)d_in[2];
    const int*   pad = (const int*)d_in[3];

    const long long CTXN = (long long)BH * SEQ * DH;
    const long long WN   = (long long)BH * SEQ * SEQ;

    float* ctxp;
    float* wp;
    if ((long long)out_size >= CTXN + WN) {
        ctxp = (float*)d_out;
        wp   = (float*)d_out + CTXN;
    } else if ((long long)out_size == WN) {
        void* s = nullptr;
        cudaGetSymbolAddress(&s, g_scratch);
        ctxp = (float*)s;
        wp   = (float*)d_out;
    } else {
        void* s = nullptr;
        cudaGetSymbolAddress(&s, g_scratch);
        ctxp = (float*)d_out;
        wp   = (float*)s;
    }

    static bool attr_done = false;
    if (!attr_done) {
        cudaFuncSetAttribute(attn_mma_kernel,
                             cudaFuncAttributeMaxDynamicSharedMemorySize,
                             SMEM_BYTES);
        attr_done = true;
    }

    split_k_kernel<<<(BH * SEQ * DH / 4 + 255) / 256, 256>>>(k);
    dim3 gt(DH / 32, SEQ / 32, BH), bt(32, 8);
    vt_split_kernel<<<gt, bt>>>(v);

    dim3 ga(SEQ / ROWS, BH), ba(NTHREADS);
    attn_mma_kernel<<<ga, ba, SMEM_BYTES>>>(q, pad, ctxp, wp);
}

// round 6
// speedup vs baseline: 6.3796x; 1.1240x over previous
#include <cuda_runtime.h>
#include <cuda_bf16.h>
#include <cstdint>

#define BH        64
#define SEQ       1024
#define DH        64
#define ROWS      32
#define NTHREADS  512
#define KTILE     128
#define NTILES    8
#define PROWB     4112              // P row stride bytes (hi[2048] | lo[2048] | pad16)
#define KROWB     144               // K/Q smem row bytes (64 bf16 + pad)
#define VROWB     272               // V^T smem row bytes (128 bf16 + pad)
#define SZ_KH     18432             // 128*144 (one K sub-buffer)
#define SZ_VH     17408             // 64*272  (one V sub-buffer)
#define KBUF      36864             // hi+lo per K/V stage buffer

// smem byte offsets
#define OFF_P    0
#define SZ_P     (ROWS * PROWB)                  // 131584
#define OFF_K0   SZ_P                            // 131584
#define OFF_K1   (OFF_K0 + KBUF)                 // 168448
#define OFF_QH   (OFF_K1 + KBUF)                 // 205312
#define SZ_QROW  (ROWS * KROWB)                  // 4608
#define OFF_QL   (OFF_QH + SZ_QROW)              // 209920
#define OFF_PAD  (OFF_QL + SZ_QROW)              // 214528
#define OFF_L    (OFF_PAD + SEQ * 4)             // 218624
#define OFF_C    (OFF_L + ROWS * 4)              // 218752
#define OFF_FLG  (OFF_C + ROWS * 4)              // 218880
#define SMEM_BYTES (OFF_FLG + 16)                // 218896 (< 227KB optin)

#define CP_COMMIT() asm volatile("cp.async.commit_group;")
#define CP_WAIT(n)  asm volatile("cp.async.wait_group %0;" :: "n"(n))

__device__ __nv_bfloat16 g_kh[(size_t)BH * SEQ * DH];
__device__ __nv_bfloat16 g_kl[(size_t)BH * SEQ * DH];
__device__ __nv_bfloat16 g_vth[(size_t)BH * DH * SEQ];   // V^T [bh][d][s]
__device__ __nv_bfloat16 g_vtl[(size_t)BH * DH * SEQ];
__device__ float g_scratch[(size_t)BH * SEQ * SEQ];

// ---------------------------------------------------------------------------
__device__ __forceinline__ uint32_t packsplit(float x, float y, uint32_t& lo) {
    __nv_bfloat16 hx = __float2bfloat16_rn(x);
    __nv_bfloat16 hy = __float2bfloat16_rn(y);
    __nv_bfloat16 lx = __float2bfloat16_rn(x - __bfloat162float(hx));
    __nv_bfloat16 ly = __float2bfloat16_rn(y - __bfloat162float(hy));
    lo = (uint32_t)__bfloat16_as_ushort(lx) | ((uint32_t)__bfloat16_as_ushort(ly) << 16);
    return (uint32_t)__bfloat16_as_ushort(hx) | ((uint32_t)__bfloat16_as_ushort(hy) << 16);
}

__device__ __forceinline__ void mma16816(float* c, const uint32_t* a,
                                         uint32_t b0, uint32_t b1) {
    asm volatile(
        "mma.sync.aligned.m16n8k16.row.col.f32.bf16.bf16.f32 "
        "{%0,%1,%2,%3},{%4,%5,%6,%7},{%8,%9},{%0,%1,%2,%3};"
        : "+f"(c[0]), "+f"(c[1]), "+f"(c[2]), "+f"(c[3])
        : "r"(a[0]), "r"(a[1]), "r"(a[2]), "r"(a[3]), "r"(b0), "r"(b1));
}

__device__ __forceinline__ void ldsm4(uint32_t* r, uint32_t addr) {
    asm volatile("ldmatrix.sync.aligned.m8n8.x4.shared.b16 {%0,%1,%2,%3},[%4];"
                 : "=r"(r[0]), "=r"(r[1]), "=r"(r[2]), "=r"(r[3]) : "r"(addr));
}
__device__ __forceinline__ void ldsm2(uint32_t& r0, uint32_t& r1, uint32_t addr) {
    asm volatile("ldmatrix.sync.aligned.m8n8.x2.shared.b16 {%0,%1},[%2];"
                 : "=r"(r0), "=r"(r1) : "r"(addr));
}

__device__ __forceinline__ float epival(float s, int col, int qrow, const int* pads) {
    bool m = (pads[col] != 0) || (col > qrow);
    return m ? 0.f : __expf(s * 0.125f);
}

__device__ __forceinline__ void stcs4(float* p, float4 v) {
    asm volatile("st.global.cs.v4.f32 [%0],{%1,%2,%3,%4};"
                 :: "l"(p), "f"(v.x), "f"(v.y), "f"(v.z), "f"(v.w));
}

// ---- cp.async tile fills ----------------------------------------------------
__device__ __forceinline__ void fill_k_tile(uint32_t sb, const __nv_bfloat16* gh,
                                            const __nv_bfloat16* gl, int tid) {
#pragma unroll
    for (int i = 0; i < 2; ++i) {
        int c = tid + i * NTHREADS;                  // 0..1023
        int row = c >> 3, seg = c & 7;
        uint32_t so = sb + row * KROWB + seg * 16;
        asm volatile("cp.async.cg.shared.global [%0], [%1], 16;"
                     :: "r"(so), "l"(gh + row * DH + seg * 8));
        asm volatile("cp.async.cg.shared.global [%0], [%1], 16;"
                     :: "r"(so + SZ_KH), "l"(gl + row * DH + seg * 8));
    }
}
__device__ __forceinline__ void fill_v_tile(uint32_t sb, const __nv_bfloat16* gh,
                                            const __nv_bfloat16* gl, int tid) {
#pragma unroll
    for (int i = 0; i < 2; ++i) {
        int c = tid + i * NTHREADS;                  // 0..1023
        int row = c >> 4, seg = c & 15;
        uint32_t so = sb + row * VROWB + seg * 16;
        asm volatile("cp.async.cg.shared.global [%0], [%1], 16;"
                     :: "r"(so), "l"(gh + (size_t)row * SEQ + seg * 8));
        asm volatile("cp.async.cg.shared.global [%0], [%1], 16;"
                     :: "r"(so + SZ_VH), "l"(gl + (size_t)row * SEQ + seg * 8));
    }
}

// ---------------------------------------------------------------------------
// prep 1: K f32 -> bf16 hi/lo (same layout)
__global__ void split_k_kernel(const float* __restrict__ k) {
    int idx = blockIdx.x * 256 + threadIdx.x;
    float4 f = ((const float4*)k)[idx];
    uint32_t l0, l1;
    uint32_t h0 = packsplit(f.x, f.y, l0);
    uint32_t h1 = packsplit(f.z, f.w, l1);
    ((uint2*)g_kh)[idx] = make_uint2(h0, h1);
    ((uint2*)g_kl)[idx] = make_uint2(l0, l1);
}

// prep 2: V f32 [bh][s][d] -> V^T bf16 hi/lo [bh][d][s]
__global__ void vt_split_kernel(const float* __restrict__ v) {
    __shared__ float tile[32][33];
    const int bh = blockIdx.z;
    const int d0 = blockIdx.x * 32;
    const int s0 = blockIdx.y * 32;
    const float* vin = v + (size_t)bh * SEQ * DH;
    const int tx = threadIdx.x, ty = threadIdx.y;
#pragma unroll
    for (int j = 0; j < 32; j += 8)
        tile[ty + j][tx] = vin[(size_t)(s0 + ty + j) * DH + (d0 + tx)];
    __syncthreads();
#pragma unroll
    for (int j = 0; j < 32; j += 8) {
        float x = tile[tx][ty + j];
        __nv_bfloat16 h = __float2bfloat16_rn(x);
        __nv_bfloat16 l = __float2bfloat16_rn(x - __bfloat162float(h));
        size_t o = (size_t)(bh * DH + d0 + ty + j) * SEQ + s0 + tx;
        g_vth[o] = h;
        g_vtl[o] = l;
    }
}

// ---------------------------------------------------------------------------
__global__ __launch_bounds__(NTHREADS, 1)
void attn_mma_kernel(const float* __restrict__ q, const int* __restrict__ pad,
                     float* __restrict__ ctx, float* __restrict__ wout) {
    extern __shared__ char pool[];
    int*   pads = (int*)(pool + OFF_PAD);
    float* Lrow = (float*)(pool + OFF_L);
    float* Crow = (float*)(pool + OFF_C);
    int*   flg  = (int*)(pool + OFF_FLG);
    const uint32_t smem0 = (uint32_t)__cvta_generic_to_shared(pool);

    const int tid  = threadIdx.x;
    const int wid  = tid >> 5;
    const int lane = tid & 31;
    const int r    = lane >> 2;
    const int tg   = lane & 3;
    const int wq   = wid >> 3;          // row block 0/1
    const int wn   = wid & 7;           // col/dim block
    const int bh   = blockIdx.y;
    const int qbase = blockIdx.x * ROWS;
    const int b    = bh >> 4;

    const __nv_bfloat16* khb = g_kh + (size_t)bh * SEQ * DH;
    const __nv_bfloat16* klb = g_kl + (size_t)bh * SEQ * DH;
    const __nv_bfloat16* vhb = g_vth + (size_t)bh * DH * SEQ;
    const __nv_bfloat16* vlb = g_vtl + (size_t)bh * DH * SEQ;

    const int qk_tiles = (qbase + ROWS - 1) / KTILE + 1;

    // prefetch K tile 0 immediately
    fill_k_tile(smem0 + OFF_K0, khb, klb, tid);
    CP_COMMIT();

    // ---- phase 0: zero P (bf16 hi/lo regions), loads -----------------------
    {
        // zero 4096B of each 4112B P row (pad bytes don't matter)
        uint4 z = make_uint4(0, 0, 0, 0);
        for (int i = tid; i < ROWS * 256; i += NTHREADS) {       // 256 uint4/row
            int row = i >> 8, seg = i & 255;
            *(uint4*)(pool + OFF_P + row * PROWB + seg * 16) = z;
        }
        if (tid < ROWS) Lrow[tid] = 0.f;
        if (tid == 0) flg[0] = 0;
        const int* pg = pad + b * SEQ;
        for (int i = tid; i < SEQ; i += NTHREADS) pads[i] = pg[i];

        // load + split Q (32x64, once per CTA)
        const float* qg = q + ((size_t)bh * SEQ + qbase) * DH;
        int row = tid >> 4, d4 = (tid & 15) * 4;
        float4 f = *(const float4*)&qg[row * DH + d4];
        uint32_t l0, l1;
        uint32_t h0 = packsplit(f.x, f.y, l0);
        uint32_t h1 = packsplit(f.z, f.w, l1);
        *(uint2*)(pool + OFF_QH + row * KROWB + d4 * 2) = make_uint2(h0, h1);
        *(uint2*)(pool + OFF_QL + row * KROWB + d4 * 2) = make_uint2(l0, l1);
    }
    __syncthreads();

    // ---- hoist Q a-fragments to registers ---------------------------------
    const uint32_t qA = smem0 + OFF_QH +
        (wq * 16 + (lane & 7) + ((lane >> 3) & 1) * 8) * KROWB + ((lane >> 4) & 1) * 16;
    uint32_t qa_h[4][4], qa_l[4][4];
#pragma unroll
    for (int ks = 0; ks < 4; ++ks) {
        ldsm4(qa_h[ks], qA + ks * 32);
        ldsm4(qa_l[ks], qA + ks * 32 + SZ_QROW);
    }

    // K/V/P LDSM relative lane addresses
    const int n0 = wn * 16;
    const uint32_t kRel =
        (n0 + (lane & 7) + ((lane >> 4) & 1) * 8) * KROWB + ((lane >> 3) & 1) * 16;
    const uint32_t vRel =
        (wn * 8 + (lane & 7)) * VROWB + ((lane >> 3) & 1) * 16;
    const uint32_t pA = smem0 + OFF_P +
        (wq * 16 + (lane & 7) + ((lane >> 3) & 1) * 8) * PROWB + ((lane >> 4) & 1) * 16;

    // ---- phase 1: QK^T + exp, store bf16-split unnormalized P --------------
    const int pr0 = wq * 16 + r;
    const int qrow0 = qbase + pr0, qrow1 = qrow0 + 8;
    float lsum0 = 0.f, lsum1 = 0.f;

    for (int t = 0; t < qk_tiles; ++t) {
        const uint32_t kb = smem0 + ((t & 1) ? OFF_K1 : OFF_K0);
        if (t + 1 < qk_tiles) {
            fill_k_tile(smem0 + (((t + 1) & 1) ? OFF_K1 : OFF_K0),
                        khb + (t + 1) * KTILE * DH, klb + (t + 1) * KTILE * DH, tid);
            CP_COMMIT();
            CP_WAIT(1);
        } else {
            CP_WAIT(0);
        }
        __syncthreads();

        float c0[4] = {0, 0, 0, 0}, c1[4] = {0, 0, 0, 0};
#pragma unroll
        for (int ks = 0; ks < 4; ++ks) {
            uint32_t kh[4], kl[4];
            ldsm4(kh, kb + kRel + ks * 32);
            ldsm4(kl, kb + SZ_KH + kRel + ks * 32);
            mma16816(c0, qa_h[ks], kh[0], kh[1]);
            mma16816(c0, qa_h[ks], kl[0], kl[1]);
            mma16816(c0, qa_l[ks], kh[0], kh[1]);
            mma16816(c1, qa_h[ks], kh[2], kh[3]);
            mma16816(c1, qa_h[ks], kl[2], kl[3]);
            mma16816(c1, qa_l[ks], kh[2], kh[3]);
        }

        int colb = t * KTILE + n0 + tg * 2;
#pragma unroll
        for (int nt = 0; nt < 2; ++nt) {
            float* cc = nt ? c1 : c0;
            int cb = colb + nt * 8;
            float e0 = epival(cc[0], cb,     qrow0, pads);
            float e1 = epival(cc[1], cb + 1, qrow0, pads);
            float e2 = epival(cc[2], cb,     qrow1, pads);
            float e3 = epival(cc[3], cb + 1, qrow1, pads);
            uint32_t lo01, lo23;
            uint32_t hi01 = packsplit(e0, e1, lo01);
            uint32_t hi23 = packsplit(e2, e3, lo23);
            char* b0p = pool + OFF_P + pr0 * PROWB + cb * 2;
            char* b1p = pool + OFF_P + (pr0 + 8) * PROWB + cb * 2;
            *(uint32_t*)(b0p)        = hi01;
            *(uint32_t*)(b0p + 2048) = lo01;
            *(uint32_t*)(b1p)        = hi23;
            *(uint32_t*)(b1p + 2048) = lo23;
            lsum0 += e0 + e1;
            lsum1 += e2 + e3;
        }
        __syncthreads();
    }

    // prefetch V tile 0 (hides behind reductions + phase 2)
    fill_v_tile(smem0 + OFF_K0, vhb, vlb, tid);
    CP_COMMIT();

    lsum0 += __shfl_xor_sync(0xffffffffu, lsum0, 1);
    lsum0 += __shfl_xor_sync(0xffffffffu, lsum0, 2);
    lsum1 += __shfl_xor_sync(0xffffffffu, lsum1, 1);
    lsum1 += __shfl_xor_sync(0xffffffffu, lsum1, 2);
    if (tg == 0) {
        atomicAdd(&Lrow[pr0], lsum0);
        atomicAdd(&Lrow[pr0 + 8], lsum1);
    }
    __syncthreads();

    // ---- phase 2a: degenerate detection -----------------------------------
    {
        int row = tid >> 4, ch = tid & 15;
        int qrow = qbase + row;
        int cnt = 0;
        for (int kx = ch * 64; kx < ch * 64 + 64; ++kx) {
            bool pd = pads[kx] != 0;
            cnt += ((kx <= qrow) ? pd : !pd) ? 1 : 0;
        }
        cnt += __shfl_xor_sync(0xffffffffu, cnt, 1);
        cnt += __shfl_xor_sync(0xffffffffu, cnt, 2);
        cnt += __shfl_xor_sync(0xffffffffu, cnt, 4);
        cnt += __shfl_xor_sync(0xffffffffu, cnt, 8);
        if (ch == 0) {
            Crow[row] = (float)cnt;
            if (Lrow[row] == 0.f) flg[0] = 1;
        }
    }
    __syncthreads();

    // ---- phase 2b: reconstruct, normalize, stream W (P untouched) ----------
    {
        int row = tid >> 4, j = tid & 15;
        int qrow = qbase + row;
        float l = Lrow[row];
        bool degen = (l == 0.f);
        float inv  = 1.f / l;
        float fill = 1.f / Crow[row];
        char* prow = pool + OFF_P + row * PROWB;
        float* wrow = wout + ((size_t)bh * SEQ + qrow) * SEQ;
#pragma unroll
        for (int i = 0; i < 16; ++i) {
            int col = (j + i * 16) * 4;
            uint2 hh = *(uint2*)(prow + col * 2);
            uint2 ll = *(uint2*)(prow + 2048 + col * 2);
            float2 fh01 = __bfloat1622float2(*(__nv_bfloat162*)&hh.x);
            float2 fh23 = __bfloat1622float2(*(__nv_bfloat162*)&hh.y);
            float2 fl01 = __bfloat1622float2(*(__nv_bfloat162*)&ll.x);
            float2 fl23 = __bfloat1622float2(*(__nv_bfloat162*)&ll.y);
            float w[4] = {fh01.x + fl01.x, fh01.y + fl01.y,
                          fh23.x + fl23.x, fh23.y + fl23.y};
            if (degen) {
#pragma unroll
                for (int u = 0; u < 4; ++u) {
                    int kx = col + u;
                    bool pd = pads[kx] != 0;
                    w[u] = ((kx <= qrow) ? pd : !pd) ? fill : 0.f;
                }
                uint32_t L01, L23;
                uint32_t H01 = packsplit(w[0], w[1], L01);
                uint32_t H23 = packsplit(w[2], w[3], L23);
                *(uint2*)(prow + col * 2)        = make_uint2(H01, H23);
                *(uint2*)(prow + 2048 + col * 2) = make_uint2(L01, L23);
            } else {
#pragma unroll
                for (int u = 0; u < 4; ++u) w[u] *= inv;
            }
            stcs4(&wrow[col], make_float4(w[0], w[1], w[2], w[3]));
        }
    }
    __syncthreads();
    const int pv_tiles = flg[0] ? NTILES : qk_tiles;

    // ---- phase 3: ctx = (P · V) * inv  (A-frags via LDSM) -------------------
    float oc[4] = {0, 0, 0, 0};
    for (int t = 0; t < pv_tiles; ++t) {
        const uint32_t vb = smem0 + ((t & 1) ? OFF_K1 : OFF_K0);
        if (t + 1 < pv_tiles) {
            fill_v_tile(smem0 + (((t + 1) & 1) ? OFF_K1 : OFF_K0),
                        vhb + (t + 1) * KTILE, vlb + (t + 1) * KTILE, tid);
            CP_COMMIT();
            CP_WAIT(1);
        } else {
            CP_WAIT(0);
        }
        __syncthreads();

#pragma unroll
        for (int ks = 0; ks < 8; ++ks) {
            uint32_t pOff = t * 256 + ks * 32;        // (t*128 + ks*16) bf16 cols
            uint32_t ah[4], al[4];
            ldsm4(ah, pA + pOff);
            ldsm4(al, pA + pOff + 2048);
            uint32_t bh0, bh1, bl0, bl1;
            ldsm2(bh0, bh1, vb + vRel + ks * 32);
            ldsm2(bl0, bl1, vb + SZ_VH + vRel + ks * 32);
            mma16816(oc, ah, bh0, bh1);
            mma16816(oc, ah, bl0, bl1);
            mma16816(oc, al, bh0, bh1);
        }
        __syncthreads();
    }

    // ---- epilogue: scale by 1/L (degen rows already normalized) ------------
    {
        float l0 = Lrow[pr0], l1 = Lrow[pr0 + 8];
        float s0 = (l0 == 0.f) ? 1.f : 1.f / l0;
        float s1 = (l1 == 0.f) ? 1.f : 1.f / l1;
        int dc = wn * 8 + tg * 2;
        float* crow = ctx + ((size_t)bh * SEQ + qbase) * DH;
        *(float2*)&crow[pr0 * DH + dc]       = make_float2(oc[0] * s0, oc[1] * s0);
        *(float2*)&crow[(pr0 + 8) * DH + dc] = make_float2(oc[2] * s1, oc[3] * s1);
    }
}

// ---------------------------------------------------------------------------
extern "C" void kernel_launch(void* const* d_in, const int* in_sizes, int n_in,
                              void* d_out, int out_size) {
    (void)in_sizes; (void)n_in;
    const float* q   = (const float*)d_in[0];
    const float* k   = (const float*)d_in[1];
    const float* v   = (const float*)d_in[2];
    const int*   pad = (const int*)d_in[3];

    const long long CTXN = (long long)BH * SEQ * DH;
    const long long WN   = (long long)BH * SEQ * SEQ;

    float* ctxp;
    float* wp;
    if ((long long)out_size >= CTXN + WN) {
        ctxp = (float*)d_out;
        wp   = (float*)d_out + CTXN;
    } else if ((long long)out_size == WN) {
        void* s = nullptr;
        cudaGetSymbolAddress(&s, g_scratch);
        ctxp = (float*)s;
        wp   = (float*)d_out;
    } else {
        void* s = nullptr;
        cudaGetSymbolAddress(&s, g_scratch);
        ctxp = (float*)d_out;
        wp   = (float*)s;
    }

    static bool attr_done = false;
    if (!attr_done) {
        cudaFuncSetAttribute(attn_mma_kernel,
                             cudaFuncAttributeMaxDynamicSharedMemorySize,
                             SMEM_BYTES);
        attr_done = true;
    }

    split_k_kernel<<<(BH * SEQ * DH / 4 + 255) / 256, 256>>>(k);
    dim3 gt(DH / 32, SEQ / 32, BH), bt(32, 8);
    vt_split_kernel<<<gt, bt>>>(v);

    dim3 ga(SEQ / ROWS, BH), ba(NTHREADS);
    attn_mma_kernel<<<ga, ba, SMEM_BYTES>>>(q, pad, ctxp, wp);
}

// round 7
// speedup vs baseline: 6.7978x; 1.0656x over previous
#include <cuda_runtime.h>
#include <cuda_bf16.h>
#include <cstdint>

#define BH        64
#define SEQ       1024
#define DH        64
#define ROWS      32
#define NTHREADS  512
#define KTILE     128
#define NTILES    8
#define PROWB     4112              // P row stride bytes (hi[2048] | lo[2048] | pad16)
#define KROWB     144               // K/Q smem row bytes (64 bf16 + pad)
#define VROWB     272               // V^T smem row bytes (128 bf16 + pad)
#define SZ_KH     18432             // 128*144 (one K sub-buffer)
#define SZ_VH     17408             // 64*272  (one V sub-buffer)
#define KBUF      36864             // K hi+lo stage
#define VBUF      34816             // V hi+lo stage

// smem byte offsets (single K buffer, single V buffer — fused loop)
#define OFF_P    0
#define SZ_P     (ROWS * PROWB)                  // 131584
#define OFF_K    SZ_P                            // 131584
#define OFF_V    (OFF_K + KBUF)                  // 168448
#define OFF_QH   (OFF_V + VBUF)                  // 203264
#define SZ_QROW  (ROWS * KROWB)                  // 4608
#define OFF_QL   (OFF_QH + SZ_QROW)              // 207872
#define OFF_PAD  (OFF_QL + SZ_QROW)              // 212480
#define OFF_L    (OFF_PAD + SEQ * 4)             // 216576
#define OFF_C    (OFF_L + ROWS * 4)              // 216704
#define OFF_FLG  (OFF_C + ROWS * 4)              // 216832
#define SMEM_BYTES (OFF_FLG + 16)                // 216848 (< 227KB optin)

#define CP_COMMIT() asm volatile("cp.async.commit_group;")
#define CP_WAIT(n)  asm volatile("cp.async.wait_group %0;" :: "n"(n))

__device__ __nv_bfloat16 g_kh[(size_t)BH * SEQ * DH];
__device__ __nv_bfloat16 g_kl[(size_t)BH * SEQ * DH];
__device__ __nv_bfloat16 g_vth[(size_t)BH * DH * SEQ];   // V^T [bh][d][s]
__device__ __nv_bfloat16 g_vtl[(size_t)BH * DH * SEQ];
__device__ float g_scratch[(size_t)BH * SEQ * SEQ];

// ---------------------------------------------------------------------------
__device__ __forceinline__ uint32_t packsplit(float x, float y, uint32_t& lo) {
    __nv_bfloat16 hx = __float2bfloat16_rn(x);
    __nv_bfloat16 hy = __float2bfloat16_rn(y);
    __nv_bfloat16 lx = __float2bfloat16_rn(x - __bfloat162float(hx));
    __nv_bfloat16 ly = __float2bfloat16_rn(y - __bfloat162float(hy));
    lo = (uint32_t)__bfloat16_as_ushort(lx) | ((uint32_t)__bfloat16_as_ushort(ly) << 16);
    return (uint32_t)__bfloat16_as_ushort(hx) | ((uint32_t)__bfloat16_as_ushort(hy) << 16);
}

__device__ __forceinline__ void mma16816(float* c, const uint32_t* a,
                                         uint32_t b0, uint32_t b1) {
    asm volatile(
        "mma.sync.aligned.m16n8k16.row.col.f32.bf16.bf16.f32 "
        "{%0,%1,%2,%3},{%4,%5,%6,%7},{%8,%9},{%0,%1,%2,%3};"
        : "+f"(c[0]), "+f"(c[1]), "+f"(c[2]), "+f"(c[3])
        : "r"(a[0]), "r"(a[1]), "r"(a[2]), "r"(a[3]), "r"(b0), "r"(b1));
}

__device__ __forceinline__ void ldsm4(uint32_t* r, uint32_t addr) {
    asm volatile("ldmatrix.sync.aligned.m8n8.x4.shared.b16 {%0,%1,%2,%3},[%4];"
                 : "=r"(r[0]), "=r"(r[1]), "=r"(r[2]), "=r"(r[3]) : "r"(addr));
}
__device__ __forceinline__ void ldsm2(uint32_t& r0, uint32_t& r1, uint32_t addr) {
    asm volatile("ldmatrix.sync.aligned.m8n8.x2.shared.b16 {%0,%1},[%2];"
                 : "=r"(r0), "=r"(r1) : "r"(addr));
}

__device__ __forceinline__ float epival(float s, int col, int qrow, const int* pads) {
    bool m = (pads[col] != 0) || (col > qrow);
    return m ? 0.f : __expf(s * 0.125f);
}

__device__ __forceinline__ void stcs4(float* p, float4 v) {
    asm volatile("st.global.cs.v4.f32 [%0],{%1,%2,%3,%4};"
                 :: "l"(p), "f"(v.x), "f"(v.y), "f"(v.z), "f"(v.w));
}

// ---- cp.async tile fills ----------------------------------------------------
__device__ __forceinline__ void fill_k_tile(uint32_t sb, const __nv_bfloat16* gh,
                                            const __nv_bfloat16* gl, int tid) {
#pragma unroll
    for (int i = 0; i < 2; ++i) {
        int c = tid + i * NTHREADS;                  // 0..1023
        int row = c >> 3, seg = c & 7;
        uint32_t so = sb + row * KROWB + seg * 16;
        asm volatile("cp.async.cg.shared.global [%0], [%1], 16;"
                     :: "r"(so), "l"(gh + row * DH + seg * 8));
        asm volatile("cp.async.cg.shared.global [%0], [%1], 16;"
                     :: "r"(so + SZ_KH), "l"(gl + row * DH + seg * 8));
    }
}
__device__ __forceinline__ void fill_v_tile(uint32_t sb, const __nv_bfloat16* gh,
                                            const __nv_bfloat16* gl, int tid) {
#pragma unroll
    for (int i = 0; i < 2; ++i) {
        int c = tid + i * NTHREADS;                  // 0..1023
        int row = c >> 4, seg = c & 15;
        uint32_t so = sb + row * VROWB + seg * 16;
        asm volatile("cp.async.cg.shared.global [%0], [%1], 16;"
                     :: "r"(so), "l"(gh + (size_t)row * SEQ + seg * 8));
        asm volatile("cp.async.cg.shared.global [%0], [%1], 16;"
                     :: "r"(so + SZ_VH), "l"(gl + (size_t)row * SEQ + seg * 8));
    }
}

// ---------------------------------------------------------------------------
// prep 1: K f32 -> bf16 hi/lo (same layout)
__global__ void split_k_kernel(const float* __restrict__ k) {
    int idx = blockIdx.x * 256 + threadIdx.x;
    float4 f = ((const float4*)k)[idx];
    uint32_t l0, l1;
    uint32_t h0 = packsplit(f.x, f.y, l0);
    uint32_t h1 = packsplit(f.z, f.w, l1);
    ((uint2*)g_kh)[idx] = make_uint2(h0, h1);
    ((uint2*)g_kl)[idx] = make_uint2(l0, l1);
}

// prep 2: V f32 [bh][s][d] -> V^T bf16 hi/lo [bh][d][s]
__global__ void vt_split_kernel(const float* __restrict__ v) {
    __shared__ float tile[32][33];
    const int bh = blockIdx.z;
    const int d0 = blockIdx.x * 32;
    const int s0 = blockIdx.y * 32;
    const float* vin = v + (size_t)bh * SEQ * DH;
    const int tx = threadIdx.x, ty = threadIdx.y;
#pragma unroll
    for (int j = 0; j < 32; j += 8)
        tile[ty + j][tx] = vin[(size_t)(s0 + ty + j) * DH + (d0 + tx)];
    __syncthreads();
#pragma unroll
    for (int j = 0; j < 32; j += 8) {
        float x = tile[tx][ty + j];
        __nv_bfloat16 h = __float2bfloat16_rn(x);
        __nv_bfloat16 l = __float2bfloat16_rn(x - __bfloat162float(h));
        size_t o = (size_t)(bh * DH + d0 + ty + j) * SEQ + s0 + tx;
        g_vth[o] = h;
        g_vtl[o] = l;
    }
}

// ---------------------------------------------------------------------------
__global__ __launch_bounds__(NTHREADS, 1)
void attn_mma_kernel(const float* __restrict__ q, const int* __restrict__ pad,
                     float* __restrict__ ctx, float* __restrict__ wout) {
    extern __shared__ char pool[];
    int*   pads = (int*)(pool + OFF_PAD);
    float* Lrow = (float*)(pool + OFF_L);
    float* Crow = (float*)(pool + OFF_C);
    int*   flg  = (int*)(pool + OFF_FLG);
    const uint32_t smem0 = (uint32_t)__cvta_generic_to_shared(pool);

    const int tid  = threadIdx.x;
    const int wid  = tid >> 5;
    const int lane = tid & 31;
    const int r    = lane >> 2;
    const int tg   = lane & 3;
    const int wq   = wid >> 3;          // row block 0/1 (QK and PV)
    const int wn   = wid & 7;           // QK col block
    const int kp   = (wid >> 1) & 3;    // PV k-part (2 ks-chunks each)
    const int np   = wid & 1;           // PV n-part (4 n-blocks = 32 dims)
    const int bh   = blockIdx.y;
    const int qbase = blockIdx.x * ROWS;
    const int b    = bh >> 4;

    const __nv_bfloat16* khb = g_kh + (size_t)bh * SEQ * DH;
    const __nv_bfloat16* klb = g_kl + (size_t)bh * SEQ * DH;
    const __nv_bfloat16* vhb = g_vth + (size_t)bh * DH * SEQ;
    const __nv_bfloat16* vlb = g_vtl + (size_t)bh * DH * SEQ;

    const int qk_tiles = (qbase + ROWS - 1) / KTILE + 1;

    // prefetch K tile 0 immediately
    fill_k_tile(smem0 + OFF_K, khb, klb, tid);
    CP_COMMIT();

    // ---- phase 0: zero P, loads -------------------------------------------
    {
        uint4 z = make_uint4(0, 0, 0, 0);
        for (int i = tid; i < ROWS * 256; i += NTHREADS) {       // 256 uint4/row
            int row = i >> 8, seg = i & 255;
            *(uint4*)(pool + OFF_P + row * PROWB + seg * 16) = z;
        }
        if (tid < ROWS) Lrow[tid] = 0.f;
        if (tid == 0) flg[0] = 0;
        const int* pg = pad + b * SEQ;
        for (int i = tid; i < SEQ; i += NTHREADS) pads[i] = pg[i];

        const float* qg = q + ((size_t)bh * SEQ + qbase) * DH;
        int row = tid >> 4, d4 = (tid & 15) * 4;
        float4 f = *(const float4*)&qg[row * DH + d4];
        uint32_t l0, l1;
        uint32_t h0 = packsplit(f.x, f.y, l0);
        uint32_t h1 = packsplit(f.z, f.w, l1);
        *(uint2*)(pool + OFF_QH + row * KROWB + d4 * 2) = make_uint2(h0, h1);
        *(uint2*)(pool + OFF_QL + row * KROWB + d4 * 2) = make_uint2(l0, l1);
    }
    __syncthreads();

    // ---- hoist Q a-fragments to registers ---------------------------------
    const uint32_t qA = smem0 + OFF_QH +
        (wq * 16 + (lane & 7) + ((lane >> 3) & 1) * 8) * KROWB + ((lane >> 4) & 1) * 16;
    uint32_t qa_h[4][4], qa_l[4][4];
#pragma unroll
    for (int ks = 0; ks < 4; ++ks) {
        ldsm4(qa_h[ks], qA + ks * 32);
        ldsm4(qa_l[ks], qA + ks * 32 + SZ_QROW);
    }

    // LDSM relative lane addresses
    const int n0 = wn * 16;
    const uint32_t kA = smem0 + OFF_K +
        (n0 + (lane & 7) + ((lane >> 4) & 1) * 8) * KROWB + ((lane >> 3) & 1) * 16;
    const uint32_t vRel0 = smem0 + OFF_V +
        (np * 32 + (lane & 7)) * VROWB + ((lane >> 3) & 1) * 16;
    const uint32_t pA = smem0 + OFF_P +
        (wq * 16 + (lane & 7) + ((lane >> 3) & 1) * 8) * PROWB + ((lane >> 4) & 1) * 16;

    const int pr0 = wq * 16 + r;
    const int qrow0 = qbase + pr0, qrow1 = qrow0 + 8;
    float lsum0 = 0.f, lsum1 = 0.f;
    float oc[4][4] = {};

    // ---- fused QK+exp+PV tile loop -----------------------------------------
    for (int t = 0; t < qk_tiles; ++t) {
        // V(t) fill overlaps QK(t) compute (V buf free: prev iter end-bar)
        fill_v_tile(smem0 + OFF_V, vhb + t * KTILE, vlb + t * KTILE, tid);
        CP_COMMIT();
        CP_WAIT(1);            // K(t) done (V(t) still pending)
        __syncthreads();

        // QK^T + exp -> P(t)
        float c0[4] = {0, 0, 0, 0}, c1[4] = {0, 0, 0, 0};
#pragma unroll
        for (int ks = 0; ks < 4; ++ks) {
            uint32_t kh[4], kl[4];
            ldsm4(kh, kA + ks * 32);
            ldsm4(kl, kA + SZ_KH + ks * 32);
            mma16816(c0, qa_h[ks], kh[0], kh[1]);
            mma16816(c0, qa_h[ks], kl[0], kl[1]);
            mma16816(c0, qa_l[ks], kh[0], kh[1]);
            mma16816(c1, qa_h[ks], kh[2], kh[3]);
            mma16816(c1, qa_h[ks], kl[2], kl[3]);
            mma16816(c1, qa_l[ks], kh[2], kh[3]);
        }
        int colb = t * KTILE + n0 + tg * 2;
#pragma unroll
        for (int nt = 0; nt < 2; ++nt) {
            float* cc = nt ? c1 : c0;
            int cb = colb + nt * 8;
            float e0 = epival(cc[0], cb,     qrow0, pads);
            float e1 = epival(cc[1], cb + 1, qrow0, pads);
            float e2 = epival(cc[2], cb,     qrow1, pads);
            float e3 = epival(cc[3], cb + 1, qrow1, pads);
            uint32_t lo01, lo23;
            uint32_t hi01 = packsplit(e0, e1, lo01);
            uint32_t hi23 = packsplit(e2, e3, lo23);
            char* b0p = pool + OFF_P + pr0 * PROWB + cb * 2;
            char* b1p = pool + OFF_P + (pr0 + 8) * PROWB + cb * 2;
            *(uint32_t*)(b0p)        = hi01;
            *(uint32_t*)(b0p + 2048) = lo01;
            *(uint32_t*)(b1p)        = hi23;
            *(uint32_t*)(b1p + 2048) = lo23;
            lsum0 += e0 + e1;
            lsum1 += e2 + e3;
        }
        __syncthreads();       // P(t) visible; K buf free

        // K(t+1) fill overlaps PV(t) compute
        if (t + 1 < qk_tiles) {
            fill_k_tile(smem0 + OFF_K, khb + (t + 1) * KTILE * DH,
                        klb + (t + 1) * KTILE * DH, tid);
            CP_COMMIT();
            CP_WAIT(1);        // V(t) done (K(t+1) pending)
        } else {
            CP_WAIT(0);
        }
        __syncthreads();       // V(t) visible

        // PV(t): warp covers (wq rows, kp 2 k-chunks, np 32 dims)
#pragma unroll
        for (int kk = 0; kk < 2; ++kk) {
            int ks = kp * 2 + kk;
            uint32_t ah[4], al[4];
            ldsm4(ah, pA + t * 256 + ks * 32);
            ldsm4(al, pA + t * 256 + ks * 32 + 2048);
            uint32_t vb2 = vRel0 + ks * 32;
#pragma unroll
            for (int nb = 0; nb < 4; ++nb) {
                uint32_t bh0, bh1, bl0, bl1;
                ldsm2(bh0, bh1, vb2 + nb * (8 * VROWB));
                ldsm2(bl0, bl1, vb2 + nb * (8 * VROWB) + SZ_VH);
                mma16816(oc[nb], ah, bh0, bh1);
                mma16816(oc[nb], ah, bl0, bl1);
                mma16816(oc[nb], al, bh0, bh1);
            }
        }
        __syncthreads();       // V buf free for next fill
    }

    // ---- Lrow reduction -----------------------------------------------------
    lsum0 += __shfl_xor_sync(0xffffffffu, lsum0, 1);
    lsum0 += __shfl_xor_sync(0xffffffffu, lsum0, 2);
    lsum1 += __shfl_xor_sync(0xffffffffu, lsum1, 1);
    lsum1 += __shfl_xor_sync(0xffffffffu, lsum1, 2);
    if (tg == 0) {
        atomicAdd(&Lrow[pr0], lsum0);
        atomicAdd(&Lrow[pr0 + 8], lsum1);
    }
    __syncthreads();

    // ---- phase 2a: degenerate detection --------------------------------------
    {
        int row = tid >> 4, ch = tid & 15;
        int qrow = qbase + row;
        int cnt = 0;
        for (int kx = ch * 64; kx < ch * 64 + 64; ++kx) {
            bool pd = pads[kx] != 0;
            cnt += ((kx <= qrow) ? pd : !pd) ? 1 : 0;
        }
        cnt += __shfl_xor_sync(0xffffffffu, cnt, 1);
        cnt += __shfl_xor_sync(0xffffffffu, cnt, 2);
        cnt += __shfl_xor_sync(0xffffffffu, cnt, 4);
        cnt += __shfl_xor_sync(0xffffffffu, cnt, 8);
        if (ch == 0) {
            Crow[row] = (float)cnt;
            if (Lrow[row] == 0.f) flg[0] = 1;
        }
    }
    __syncthreads();

    // ---- phase 2b: reconstruct, normalize, stream W --------------------------
    {
        int row = tid >> 4, j = tid & 15;
        int qrow = qbase + row;
        float l = Lrow[row];
        bool degen = (l == 0.f);
        float inv  = 1.f / l;
        float fill = 1.f / Crow[row];
        char* prow = pool + OFF_P + row * PROWB;
        float* wrow = wout + ((size_t)bh * SEQ + qrow) * SEQ;
#pragma unroll
        for (int i = 0; i < 16; ++i) {
            int col = (j + i * 16) * 4;
            uint2 hh = *(uint2*)(prow + col * 2);
            uint2 ll = *(uint2*)(prow + 2048 + col * 2);
            float2 fh01 = __bfloat1622float2(*(__nv_bfloat162*)&hh.x);
            float2 fh23 = __bfloat1622float2(*(__nv_bfloat162*)&hh.y);
            float2 fl01 = __bfloat1622float2(*(__nv_bfloat162*)&ll.x);
            float2 fl23 = __bfloat1622float2(*(__nv_bfloat162*)&ll.y);
            float w[4] = {fh01.x + fl01.x, fh01.y + fl01.y,
                          fh23.x + fl23.x, fh23.y + fl23.y};
            if (degen) {
#pragma unroll
                for (int u = 0; u < 4; ++u) {
                    int kx = col + u;
                    bool pd = pads[kx] != 0;
                    w[u] = ((kx <= qrow) ? pd : !pd) ? fill : 0.f;
                }
                uint32_t L01, L23;
                uint32_t H01 = packsplit(w[0], w[1], L01);
                uint32_t H23 = packsplit(w[2], w[3], L23);
                *(uint2*)(prow + col * 2)        = make_uint2(H01, H23);
                *(uint2*)(prow + 2048 + col * 2) = make_uint2(L01, L23);
            } else {
#pragma unroll
                for (int u = 0; u < 4; ++u) w[u] *= inv;
            }
            stcs4(&wrow[col], make_float4(w[0], w[1], w[2], w[3]));
        }
    }
    __syncthreads();

    // ---- degenerate fallback: recompute PV over all tiles from stored P ------
    if (flg[0]) {
#pragma unroll
        for (int nb = 0; nb < 4; ++nb)
#pragma unroll
            for (int i = 0; i < 4; ++i) oc[nb][i] = 0.f;
        for (int t = 0; t < NTILES; ++t) {
            fill_v_tile(smem0 + OFF_V, vhb + t * KTILE, vlb + t * KTILE, tid);
            CP_COMMIT();
            CP_WAIT(0);
            __syncthreads();
#pragma unroll
            for (int kk = 0; kk < 2; ++kk) {
                int ks = kp * 2 + kk;
                uint32_t ah[4], al[4];
                ldsm4(ah, pA + t * 256 + ks * 32);
                ldsm4(al, pA + t * 256 + ks * 32 + 2048);
                uint32_t vb2 = vRel0 + ks * 32;
#pragma unroll
                for (int nb = 0; nb < 4; ++nb) {
                    uint32_t bh0, bh1, bl0, bl1;
                    ldsm2(bh0, bh1, vb2 + nb * (8 * VROWB));
                    ldsm2(bl0, bl1, vb2 + nb * (8 * VROWB) + SZ_VH);
                    mma16816(oc[nb], ah, bh0, bh1);
                    mma16816(oc[nb], ah, bl0, bl1);
                    mma16816(oc[nb], al, bh0, bh1);
                }
            }
            __syncthreads();
        }
    }

    // ---- cross-warp k-part reduction + scaled epilogue ------------------------
    // partials: word addr = kp*2048 + (wq*2+np)*512 + v*32 + lane  (conflict-free)
    {
        char* base = pool + OFF_P + kp * 8192 + (wq * 2 + np) * 2048 + lane * 4;
#pragma unroll
        for (int nb = 0; nb < 4; ++nb)
#pragma unroll
            for (int i = 0; i < 4; ++i)
                *(float*)(base + (nb * 4 + i) * 128) = oc[nb][i];
    }
    __syncthreads();
    {
        int l = tid & 31, g = tid >> 7, vset = (tid >> 5) & 3;
        int rr = l >> 2, tg4 = l & 3;
        int dim0 = (g & 1) * 32 + vset * 8 + tg4 * 2;
        int rowa = (g >> 1) * 16 + rr;
        int rowb = rowa + 8;
        float acc[4] = {0.f, 0.f, 0.f, 0.f};
#pragma unroll
        for (int kpp = 0; kpp < 4; ++kpp) {
            char* bp = pool + OFF_P + kpp * 8192 + g * 2048 + l * 4;
#pragma unroll
            for (int i = 0; i < 4; ++i)
                acc[i] += *(float*)(bp + (vset * 4 + i) * 128);
        }
        float la = Lrow[rowa], lb = Lrow[rowb];
        float sa = (la == 0.f) ? 1.f : 1.f / la;
        float sb = (lb == 0.f) ? 1.f : 1.f / lb;
        float* crow = ctx + ((size_t)bh * SEQ + qbase) * DH;
        *(float2*)&crow[rowa * DH + dim0] = make_float2(acc[0] * sa, acc[1] * sa);
        *(float2*)&crow[rowb * DH + dim0] = make_float2(acc[2] * sb, acc[3] * sb);
    }
}

// ---------------------------------------------------------------------------
extern "C" void kernel_launch(void* const* d_in, const int* in_sizes, int n_in,
                              void* d_out, int out_size) {
    (void)in_sizes; (void)n_in;
    const float* q   = (const float*)d_in[0];
    const float* k   = (const float*)d_in[1];
    const float* v   = (const float*)d_in[2];
    const int*   pad = (const int*)d_in[3];

    const long long CTXN = (long long)BH * SEQ * DH;
    const long long WN   = (long long)BH * SEQ * SEQ;

    float* ctxp;
    float* wp;
    if ((long long)out_size >= CTXN + WN) {
        ctxp = (float*)d_out;
        wp   = (float*)d_out + CTXN;
    } else if ((long long)out_size == WN) {
        void* s = nullptr;
        cudaGetSymbolAddress(&s, g_scratch);
        ctxp = (float*)s;
        wp   = (float*)d_out;
    } else {
        void* s = nullptr;
        cudaGetSymbolAddress(&s, g_scratch);
        ctxp = (float*)d_out;
        wp   = (float*)s;
    }

    static bool attr_done = false;
    if (!attr_done) {
        cudaFuncSetAttribute(attn_mma_kernel,
                             cudaFuncAttributeMaxDynamicSharedMemorySize,
                             SMEM_BYTES);
        attr_done = true;
    }

    split_k_kernel<<<(BH * SEQ * DH / 4 + 255) / 256, 256>>>(k);
    dim3 gt(DH / 32, SEQ / 32, BH), bt(32, 8);
    vt_split_kernel<<<gt, bt>>>(v);

    dim3 ga(SEQ / ROWS, BH), ba(NTHREADS);
    attn_mma_kernel<<<ga, ba, SMEM_BYTES>>>(q, pad, ctxp, wp);
}

// round 8
// speedup vs baseline: 6.9836x; 1.0273x over previous
#include <cuda_runtime.h>
#include <cuda_bf16.h>
#include <cstdint>

#define BH        64
#define SEQ       1024
#define DH        64
#define ROWS      32
#define NTHREADS  512
#define KTILE     128
#define NTILES    8
#define PROWB     4112              // P row stride bytes (hi[2048] | lo[2048] | pad16)
#define KROWB     144               // K/Q smem row bytes (64 bf16 + pad)
#define VROWB     272               // V^T smem row bytes (128 bf16 + pad)
#define SZ_KH     18432             // 128*144 (one K sub-buffer)
#define SZ_VH     17408             // 64*272  (one V sub-buffer)
#define KBUF      36864             // K hi+lo stage
#define VBUF      34816             // V hi+lo stage

// smem byte offsets (single K buffer, single V buffer — fused loop)
#define OFF_P    0
#define SZ_P     (ROWS * PROWB)                  // 131584
#define OFF_K    SZ_P                            // 131584
#define OFF_V    (OFF_K + KBUF)                  // 168448
#define OFF_QH   (OFF_V + VBUF)                  // 203264
#define SZ_QROW  (ROWS * KROWB)                  // 4608
#define OFF_QL   (OFF_QH + SZ_QROW)              // 207872
#define OFF_PAD  (OFF_QL + SZ_QROW)              // 212480
#define OFF_L    (OFF_PAD + SEQ * 4)             // 216576
#define OFF_C    (OFF_L + ROWS * 4)              // 216704
#define OFF_FLG  (OFF_C + ROWS * 4)              // 216832
#define SMEM_BYTES (OFF_FLG + 16)                // 216848 (< 227KB optin)

#define CP_COMMIT() asm volatile("cp.async.commit_group;")
#define CP_WAIT(n)  asm volatile("cp.async.wait_group %0;" :: "n"(n))

__device__ __nv_bfloat16 g_kh[(size_t)BH * SEQ * DH];
__device__ __nv_bfloat16 g_kl[(size_t)BH * SEQ * DH];
__device__ __nv_bfloat16 g_vth[(size_t)BH * DH * SEQ];   // V^T [bh][d][s]
__device__ __nv_bfloat16 g_vtl[(size_t)BH * DH * SEQ];
__device__ float g_scratch[(size_t)BH * SEQ * SEQ];

// ---------------------------------------------------------------------------
__device__ __forceinline__ uint32_t packsplit(float x, float y, uint32_t& lo) {
    __nv_bfloat16 hx = __float2bfloat16_rn(x);
    __nv_bfloat16 hy = __float2bfloat16_rn(y);
    __nv_bfloat16 lx = __float2bfloat16_rn(x - __bfloat162float(hx));
    __nv_bfloat16 ly = __float2bfloat16_rn(y - __bfloat162float(hy));
    lo = (uint32_t)__bfloat16_as_ushort(lx) | ((uint32_t)__bfloat16_as_ushort(ly) << 16);
    return (uint32_t)__bfloat16_as_ushort(hx) | ((uint32_t)__bfloat16_as_ushort(hy) << 16);
}

__device__ __forceinline__ void mma16816(float* c, const uint32_t* a,
                                         uint32_t b0, uint32_t b1) {
    asm volatile(
        "mma.sync.aligned.m16n8k16.row.col.f32.bf16.bf16.f32 "
        "{%0,%1,%2,%3},{%4,%5,%6,%7},{%8,%9},{%0,%1,%2,%3};"
        : "+f"(c[0]), "+f"(c[1]), "+f"(c[2]), "+f"(c[3])
        : "r"(a[0]), "r"(a[1]), "r"(a[2]), "r"(a[3]), "r"(b0), "r"(b1));
}

__device__ __forceinline__ void ldsm4(uint32_t* r, uint32_t addr) {
    asm volatile("ldmatrix.sync.aligned.m8n8.x4.shared.b16 {%0,%1,%2,%3},[%4];"
                 : "=r"(r[0]), "=r"(r[1]), "=r"(r[2]), "=r"(r[3]) : "r"(addr));
}
__device__ __forceinline__ void ldsm2(uint32_t& r0, uint32_t& r1, uint32_t addr) {
    asm volatile("ldmatrix.sync.aligned.m8n8.x2.shared.b16 {%0,%1},[%2];"
                 : "=r"(r0), "=r"(r1) : "r"(addr));
}

__device__ __forceinline__ float epival(float s, int col, int qrow, const int* pads) {
    bool m = (pads[col] != 0) || (col > qrow);
    return m ? 0.f : __expf(s * 0.125f);
}

// ---- cp.async tile fills ----------------------------------------------------
__device__ __forceinline__ void fill_k_tile(uint32_t sb, const __nv_bfloat16* gh,
                                            const __nv_bfloat16* gl, int tid) {
#pragma unroll
    for (int i = 0; i < 2; ++i) {
        int c = tid + i * NTHREADS;                  // 0..1023
        int row = c >> 3, seg = c & 7;
        uint32_t so = sb + row * KROWB + seg * 16;
        asm volatile("cp.async.cg.shared.global [%0], [%1], 16;"
                     :: "r"(so), "l"(gh + row * DH + seg * 8));
        asm volatile("cp.async.cg.shared.global [%0], [%1], 16;"
                     :: "r"(so + SZ_KH), "l"(gl + row * DH + seg * 8));
    }
}
__device__ __forceinline__ void fill_v_tile(uint32_t sb, const __nv_bfloat16* gh,
                                            const __nv_bfloat16* gl, int tid) {
#pragma unroll
    for (int i = 0; i < 2; ++i) {
        int c = tid + i * NTHREADS;                  // 0..1023
        int row = c >> 4, seg = c & 15;
        uint32_t so = sb + row * VROWB + seg * 16;
        asm volatile("cp.async.cg.shared.global [%0], [%1], 16;"
                     :: "r"(so), "l"(gh + (size_t)row * SEQ + seg * 8));
        asm volatile("cp.async.cg.shared.global [%0], [%1], 16;"
                     :: "r"(so + SZ_VH), "l"(gl + (size_t)row * SEQ + seg * 8));
    }
}

// ---------------------------------------------------------------------------
// prep 1: K f32 -> bf16 hi/lo (same layout)
__global__ void split_k_kernel(const float* __restrict__ k) {
    int idx = blockIdx.x * 256 + threadIdx.x;
    float4 f = ((const float4*)k)[idx];
    uint32_t l0, l1;
    uint32_t h0 = packsplit(f.x, f.y, l0);
    uint32_t h1 = packsplit(f.z, f.w, l1);
    ((uint2*)g_kh)[idx] = make_uint2(h0, h1);
    ((uint2*)g_kl)[idx] = make_uint2(l0, l1);
}

// prep 2: V f32 [bh][s][d] -> V^T bf16 hi/lo [bh][d][s]
__global__ void vt_split_kernel(const float* __restrict__ v) {
    __shared__ float tile[32][33];
    const int bh = blockIdx.z;
    const int d0 = blockIdx.x * 32;
    const int s0 = blockIdx.y * 32;
    const float* vin = v + (size_t)bh * SEQ * DH;
    const int tx = threadIdx.x, ty = threadIdx.y;
#pragma unroll
    for (int j = 0; j < 32; j += 8)
        tile[ty + j][tx] = vin[(size_t)(s0 + ty + j) * DH + (d0 + tx)];
    __syncthreads();
#pragma unroll
    for (int j = 0; j < 32; j += 8) {
        float x = tile[tx][ty + j];
        __nv_bfloat16 h = __float2bfloat16_rn(x);
        __nv_bfloat16 l = __float2bfloat16_rn(x - __bfloat162float(h));
        size_t o = (size_t)(bh * DH + d0 + ty + j) * SEQ + s0 + tx;
        g_vth[o] = h;
        g_vtl[o] = l;
    }
}

// ---------------------------------------------------------------------------
__global__ __launch_bounds__(NTHREADS, 1)
void attn_mma_kernel(const float* __restrict__ q, const int* __restrict__ pad,
                     float* __restrict__ ctx, float* __restrict__ wout) {
    extern __shared__ char pool[];
    int*   pads = (int*)(pool + OFF_PAD);
    float* Lrow = (float*)(pool + OFF_L);
    float* Crow = (float*)(pool + OFF_C);
    int*   flg  = (int*)(pool + OFF_FLG);
    const uint32_t smem0 = (uint32_t)__cvta_generic_to_shared(pool);

    const int tid  = threadIdx.x;
    const int wid  = tid >> 5;
    const int lane = tid & 31;
    const int r    = lane >> 2;
    const int tg   = lane & 3;
    const int wq   = wid >> 3;          // row block 0/1 (QK and PV)
    const int wn   = wid & 7;           // QK col block
    const int kp   = (wid >> 1) & 3;    // PV k-part (2 ks-chunks each)
    const int np   = wid & 1;           // PV n-part (4 n-blocks = 32 dims)
    const int bh   = blockIdx.y;
    const int qbase = blockIdx.x * ROWS;
    const int b    = bh >> 4;

    const __nv_bfloat16* khb = g_kh + (size_t)bh * SEQ * DH;
    const __nv_bfloat16* klb = g_kl + (size_t)bh * SEQ * DH;
    const __nv_bfloat16* vhb = g_vth + (size_t)bh * DH * SEQ;
    const __nv_bfloat16* vlb = g_vtl + (size_t)bh * DH * SEQ;

    const int qk_tiles = (qbase + ROWS - 1) / KTILE + 1;

    // prefetch K tile 0 immediately
    fill_k_tile(smem0 + OFF_K, khb, klb, tid);
    CP_COMMIT();

    // ---- phase 0: zero P, loads -------------------------------------------
    {
        uint4 z = make_uint4(0, 0, 0, 0);
        for (int i = tid; i < ROWS * 256; i += NTHREADS) {       // 256 uint4/row
            int row = i >> 8, seg = i & 255;
            *(uint4*)(pool + OFF_P + row * PROWB + seg * 16) = z;
        }
        if (tid < ROWS) Lrow[tid] = 0.f;
        if (tid == 0) flg[0] = 0;
        const int* pg = pad + b * SEQ;
        for (int i = tid; i < SEQ; i += NTHREADS) pads[i] = pg[i];

        const float* qg = q + ((size_t)bh * SEQ + qbase) * DH;
        int row = tid >> 4, d4 = (tid & 15) * 4;
        float4 f = *(const float4*)&qg[row * DH + d4];
        uint32_t l0, l1;
        uint32_t h0 = packsplit(f.x, f.y, l0);
        uint32_t h1 = packsplit(f.z, f.w, l1);
        *(uint2*)(pool + OFF_QH + row * KROWB + d4 * 2) = make_uint2(h0, h1);
        *(uint2*)(pool + OFF_QL + row * KROWB + d4 * 2) = make_uint2(l0, l1);
    }
    __syncthreads();

    // ---- hoist Q a-fragments to registers ---------------------------------
    const uint32_t qA = smem0 + OFF_QH +
        (wq * 16 + (lane & 7) + ((lane >> 3) & 1) * 8) * KROWB + ((lane >> 4) & 1) * 16;
    uint32_t qa_h[4][4], qa_l[4][4];
#pragma unroll
    for (int ks = 0; ks < 4; ++ks) {
        ldsm4(qa_h[ks], qA + ks * 32);
        ldsm4(qa_l[ks], qA + ks * 32 + SZ_QROW);
    }

    // LDSM relative lane addresses
    const int n0 = wn * 16;
    const uint32_t kA = smem0 + OFF_K +
        (n0 + (lane & 7) + ((lane >> 4) & 1) * 8) * KROWB + ((lane >> 3) & 1) * 16;
    const uint32_t vRel0 = smem0 + OFF_V +
        (np * 32 + (lane & 7)) * VROWB + ((lane >> 3) & 1) * 16;
    const uint32_t pA = smem0 + OFF_P +
        (wq * 16 + (lane & 7) + ((lane >> 3) & 1) * 8) * PROWB + ((lane >> 4) & 1) * 16;

    const int pr0 = wq * 16 + r;
    const int qrow0 = qbase + pr0, qrow1 = qrow0 + 8;
    float lsum0 = 0.f, lsum1 = 0.f;
    float oc[4][4] = {};

    // ---- fused QK+exp+PV tile loop -----------------------------------------
    for (int t = 0; t < qk_tiles; ++t) {
        // V(t) fill overlaps QK(t) compute (V buf free: prev iter end-bar)
        fill_v_tile(smem0 + OFF_V, vhb + t * KTILE, vlb + t * KTILE, tid);
        CP_COMMIT();
        CP_WAIT(1);            // K(t) done (V(t) still pending)
        __syncthreads();

        // QK^T + exp -> P(t)
        float c0[4] = {0, 0, 0, 0}, c1[4] = {0, 0, 0, 0};
#pragma unroll
        for (int ks = 0; ks < 4; ++ks) {
            uint32_t kh[4], kl[4];
            ldsm4(kh, kA + ks * 32);
            ldsm4(kl, kA + SZ_KH + ks * 32);
            mma16816(c0, qa_h[ks], kh[0], kh[1]);
            mma16816(c0, qa_h[ks], kl[0], kl[1]);
            mma16816(c0, qa_l[ks], kh[0], kh[1]);
            mma16816(c1, qa_h[ks], kh[2], kh[3]);
            mma16816(c1, qa_h[ks], kl[2], kl[3]);
            mma16816(c1, qa_l[ks], kh[2], kh[3]);
        }
        int colb = t * KTILE + n0 + tg * 2;
#pragma unroll
        for (int nt = 0; nt < 2; ++nt) {
            float* cc = nt ? c1 : c0;
            int cb = colb + nt * 8;
            float e0 = epival(cc[0], cb,     qrow0, pads);
            float e1 = epival(cc[1], cb + 1, qrow0, pads);
            float e2 = epival(cc[2], cb,     qrow1, pads);
            float e3 = epival(cc[3], cb + 1, qrow1, pads);
            uint32_t lo01, lo23;
            uint32_t hi01 = packsplit(e0, e1, lo01);
            uint32_t hi23 = packsplit(e2, e3, lo23);
            char* b0p = pool + OFF_P + pr0 * PROWB + cb * 2;
            char* b1p = pool + OFF_P + (pr0 + 8) * PROWB + cb * 2;
            *(uint32_t*)(b0p)        = hi01;
            *(uint32_t*)(b0p + 2048) = lo01;
            *(uint32_t*)(b1p)        = hi23;
            *(uint32_t*)(b1p + 2048) = lo23;
            lsum0 += e0 + e1;
            lsum1 += e2 + e3;
        }
        __syncthreads();       // P(t) visible; K buf free

        // K(t+1) fill overlaps PV(t) compute
        if (t + 1 < qk_tiles) {
            fill_k_tile(smem0 + OFF_K, khb + (t + 1) * KTILE * DH,
                        klb + (t + 1) * KTILE * DH, tid);
            CP_COMMIT();
            CP_WAIT(1);        // V(t) done (K(t+1) pending)
        } else {
            CP_WAIT(0);
        }
        __syncthreads();       // V(t) visible

        // PV(t): warp covers (wq rows, kp 2 k-chunks, np 32 dims)
#pragma unroll
        for (int kk = 0; kk < 2; ++kk) {
            int ks = kp * 2 + kk;
            uint32_t ah[4], al[4];
            ldsm4(ah, pA + t * 256 + ks * 32);
            ldsm4(al, pA + t * 256 + ks * 32 + 2048);
            uint32_t vb2 = vRel0 + ks * 32;
#pragma unroll
            for (int nb = 0; nb < 4; ++nb) {
                uint32_t bh0, bh1, bl0, bl1;
                ldsm2(bh0, bh1, vb2 + nb * (8 * VROWB));
                ldsm2(bl0, bl1, vb2 + nb * (8 * VROWB) + SZ_VH);
                mma16816(oc[nb], ah, bh0, bh1);
                mma16816(oc[nb], ah, bl0, bl1);
                mma16816(oc[nb], al, bh0, bh1);
            }
        }
        __syncthreads();       // V buf free for next fill
    }

    // ---- Lrow reduction -----------------------------------------------------
    lsum0 += __shfl_xor_sync(0xffffffffu, lsum0, 1);
    lsum0 += __shfl_xor_sync(0xffffffffu, lsum0, 2);
    lsum1 += __shfl_xor_sync(0xffffffffu, lsum1, 1);
    lsum1 += __shfl_xor_sync(0xffffffffu, lsum1, 2);
    if (tg == 0) {
        atomicAdd(&Lrow[pr0], lsum0);
        atomicAdd(&Lrow[pr0 + 8], lsum1);
    }
    __syncthreads();

    // ---- phase 2a: degenerate detection --------------------------------------
    {
        int row = tid >> 4, ch = tid & 15;
        int qrow = qbase + row;
        int cnt = 0;
        for (int kx = ch * 64; kx < ch * 64 + 64; ++kx) {
            bool pd = pads[kx] != 0;
            cnt += ((kx <= qrow) ? pd : !pd) ? 1 : 0;
        }
        cnt += __shfl_xor_sync(0xffffffffu, cnt, 1);
        cnt += __shfl_xor_sync(0xffffffffu, cnt, 2);
        cnt += __shfl_xor_sync(0xffffffffu, cnt, 4);
        cnt += __shfl_xor_sync(0xffffffffu, cnt, 8);
        if (ch == 0) {
            Crow[row] = (float)cnt;
            if (Lrow[row] == 0.f) flg[0] = 1;
        }
    }
    __syncthreads();

    // ---- phase 2b: reconstruct+normalize -> smem stage -> bulk store ---------
    // W block is one contiguous 512KB gmem region. 4 chunks x (8 rows = 32KB),
    // double-buffered in the free K+V staging area; bulk engine does the STG.
    {
        const int rloc = tid >> 6;          // 0..7 row within chunk
        const int cidx = tid & 63;          // 64 threads per row
        float* wbase = wout + ((size_t)bh * SEQ + qbase) * SEQ;
#pragma unroll
        for (int g = 0; g < 4; ++g) {
            const uint32_t sbuf = smem0 + OFF_K + (g & 1) * 32768;
            if (g >= 2) {
                if (tid == 0)
                    asm volatile("cp.async.bulk.wait_group.read 1;" ::: "memory");
                __syncthreads();             // buffer (g&1) reusable
            }
            const int row = g * 8 + rloc;
            const int qrow = qbase + row;
            const float l = Lrow[row];
            const bool degen = (l == 0.f);
            const float inv  = 1.f / l;
            const float fill = 1.f / Crow[row];
            char* prow = pool + OFF_P + row * PROWB;
#pragma unroll
            for (int j = 0; j < 4; ++j) {
                int col = j * 256 + cidx * 4;
                uint2 hh = *(uint2*)(prow + col * 2);
                uint2 ll = *(uint2*)(prow + 2048 + col * 2);
                float2 fh01 = __bfloat1622float2(*(__nv_bfloat162*)&hh.x);
                float2 fh23 = __bfloat1622float2(*(__nv_bfloat162*)&hh.y);
                float2 fl01 = __bfloat1622float2(*(__nv_bfloat162*)&ll.x);
                float2 fl23 = __bfloat1622float2(*(__nv_bfloat162*)&ll.y);
                float w[4] = {fh01.x + fl01.x, fh01.y + fl01.y,
                              fh23.x + fl23.x, fh23.y + fl23.y};
                if (degen) {
#pragma unroll
                    for (int u = 0; u < 4; ++u) {
                        int kx = col + u;
                        bool pd = pads[kx] != 0;
                        w[u] = ((kx <= qrow) ? pd : !pd) ? fill : 0.f;
                    }
                    uint32_t L01, L23;
                    uint32_t H01 = packsplit(w[0], w[1], L01);
                    uint32_t H23 = packsplit(w[2], w[3], L23);
                    *(uint2*)(prow + col * 2)        = make_uint2(H01, H23);
                    *(uint2*)(prow + 2048 + col * 2) = make_uint2(L01, L23);
                } else {
#pragma unroll
                    for (int u = 0; u < 4; ++u) w[u] *= inv;
                }
                uint32_t saddr = sbuf + rloc * 4096 + col * 4;
                asm volatile("st.shared.v4.f32 [%0],{%1,%2,%3,%4};"
                             :: "r"(saddr), "f"(w[0]), "f"(w[1]),
                                "f"(w[2]), "f"(w[3]));
            }
            __syncthreads();                 // chunk staged
            if (tid == 0) {
                asm volatile("fence.proxy.async.shared::cta;" ::: "memory");
                asm volatile(
                    "cp.async.bulk.global.shared::cta.bulk_group [%0], [%1], %2;"
                    :: "l"(wbase + g * 8192), "r"(sbuf), "r"(32768) : "memory");
                asm volatile("cp.async.bulk.commit_group;" ::: "memory");
            }
        }
        if (tid == 0)
            asm volatile("cp.async.bulk.wait_group.read 0;" ::: "memory");
        __syncthreads();                     // stage area (incl. V buf) free
    }

    // ---- degenerate fallback: recompute PV over all tiles from stored P ------
    if (flg[0]) {
#pragma unroll
        for (int nb = 0; nb < 4; ++nb)
#pragma unroll
            for (int i = 0; i < 4; ++i) oc[nb][i] = 0.f;
        for (int t = 0; t < NTILES; ++t) {
            fill_v_tile(smem0 + OFF_V, vhb + t * KTILE, vlb + t * KTILE, tid);
            CP_COMMIT();
            CP_WAIT(0);
            __syncthreads();
#pragma unroll
            for (int kk = 0; kk < 2; ++kk) {
                int ks = kp * 2 + kk;
                uint32_t ah[4], al[4];
                ldsm4(ah, pA + t * 256 + ks * 32);
                ldsm4(al, pA + t * 256 + ks * 32 + 2048);
                uint32_t vb2 = vRel0 + ks * 32;
#pragma unroll
                for (int nb = 0; nb < 4; ++nb) {
                    uint32_t bh0, bh1, bl0, bl1;
                    ldsm2(bh0, bh1, vb2 + nb * (8 * VROWB));
                    ldsm2(bl0, bl1, vb2 + nb * (8 * VROWB) + SZ_VH);
                    mma16816(oc[nb], ah, bh0, bh1);
                    mma16816(oc[nb], ah, bl0, bl1);
                    mma16816(oc[nb], al, bh0, bh1);
                }
            }
            __syncthreads();
        }
    }

    // ---- cross-warp k-part reduction + scaled epilogue ------------------------
    // partials: word addr = kp*2048 + (wq*2+np)*512 + v*32 + lane  (conflict-free)
    {
        char* base = pool + OFF_P + kp * 8192 + (wq * 2 + np) * 2048 + lane * 4;
#pragma unroll
        for (int nb = 0; nb < 4; ++nb)
#pragma unroll
            for (int i = 0; i < 4; ++i)
                *(float*)(base + (nb * 4 + i) * 128) = oc[nb][i];
    }
    __syncthreads();
    {
        int l = tid & 31, g = tid >> 7, vset = (tid >> 5) & 3;
        int rr = l >> 2, tg4 = l & 3;
        int dim0 = (g & 1) * 32 + vset * 8 + tg4 * 2;
        int rowa = (g >> 1) * 16 + rr;
        int rowb = rowa + 8;
        float acc[4] = {0.f, 0.f, 0.f, 0.f};
#pragma unroll
        for (int kpp = 0; kpp < 4; ++kpp) {
            char* bp = pool + OFF_P + kpp * 8192 + g * 2048 + l * 4;
#pragma unroll
            for (int i = 0; i < 4; ++i)
                acc[i] += *(float*)(bp + (vset * 4 + i) * 128);
        }
        float la = Lrow[rowa], lb = Lrow[rowb];
        float sa = (la == 0.f) ? 1.f : 1.f / la;
        float sb = (lb == 0.f) ? 1.f : 1.f / lb;
        float* crow = ctx + ((size_t)bh * SEQ + qbase) * DH;
        *(float2*)&crow[rowa * DH + dim0] = make_float2(acc[0] * sa, acc[1] * sa);
        *(float2*)&crow[rowb * DH + dim0] = make_float2(acc[2] * sb, acc[3] * sb);
    }
}

// ---------------------------------------------------------------------------
extern "C" void kernel_launch(void* const* d_in, const int* in_sizes, int n_in,
                              void* d_out, int out_size) {
    (void)in_sizes; (void)n_in;
    const float* q   = (const float*)d_in[0];
    const float* k   = (const float*)d_in[1];
    const float* v   = (const float*)d_in[2];
    const int*   pad = (const int*)d_in[3];

    const long long CTXN = (long long)BH * SEQ * DH;
    const long long WN   = (long long)BH * SEQ * SEQ;

    float* ctxp;
    float* wp;
    if ((long long)out_size >= CTXN + WN) {
        ctxp = (float*)d_out;
        wp   = (float*)d_out + CTXN;
    } else if ((long long)out_size == WN) {
        void* s = nullptr;
        cudaGetSymbolAddress(&s, g_scratch);
        ctxp = (float*)s;
        wp   = (float*)d_out;
    } else {
        void* s = nullptr;
        cudaGetSymbolAddress(&s, g_scratch);
        ctxp = (float*)d_out;
        wp   = (float*)s;
    }

    static bool attr_done = false;
    if (!attr_done) {
        cudaFuncSetAttribute(attn_mma_kernel,
                             cudaFuncAttributeMaxDynamicSharedMemorySize,
                             SMEM_BYTES);
        attr_done = true;
    }

    split_k_kernel<<<(BH * SEQ * DH / 4 + 255) / 256, 256>>>(k);
    dim3 gt(DH / 32, SEQ / 32, BH), bt(32, 8);
    vt_split_kernel<<<gt, bt>>>(v);

    dim3 ga(SEQ / ROWS, BH), ba(NTHREADS);
    attn_mma_kernel<<<ga, ba, SMEM_BYTES>>>(q, pad, ctxp, wp);
}

// round 9
// speedup vs baseline: 7.9172x; 1.1337x over previous
#include <cuda_runtime.h>
#include <cuda_bf16.h>
#include <cstdint>

#define BH        64
#define SEQ       1024
#define DH        64
#define ROWS      32
#define NTHREADS  512
#define KTILE     128
#define NTILES    8
#define PROWB     4112              // P row stride bytes (hi[2048] | lo[2048] | pad16)
#define QROWB     144               // Q smem row bytes (64 bf16 + pad)
#define SZ_KH     16384             // K hi sub-buffer (128 rows x 128B, swizzled)
#define SZ_VH     16384             // V hi sub-buffer (64 rows x 256B, swizzled)

// smem byte offsets
#define OFF_P    0
#define SZ_P     (ROWS * PROWB)                  // 131584
#define OFF_K    SZ_P                            // 131584 (hi 16K | lo 16K)
#define OFF_V    (OFF_K + 2 * SZ_KH)             // 164352 (hi 16K | lo 16K)
#define OFF_QH   (OFF_V + 2 * SZ_VH)             // 197120
#define SZ_QROW  (ROWS * QROWB)                  // 4608
#define OFF_QL   (OFF_QH + SZ_QROW)              // 201728
#define OFF_PAD  (OFF_QL + SZ_QROW)              // 206336
#define OFF_L    (OFF_PAD + SEQ * 4)             // 210432
#define OFF_C    (OFF_L + ROWS * 4)              // 210560
#define OFF_FLG  (OFF_C + ROWS * 4)              // 210688
#define OFF_MB   (OFF_FLG + 16)                  // 210704 (mbK, mbV)
#define SMEM_BYTES (OFF_MB + 16)                 // 210720 (< 227KB optin)

__device__ __nv_bfloat16 g_kh[(size_t)BH * SEQ * DH];   // tile-contig, swizzled
__device__ __nv_bfloat16 g_kl[(size_t)BH * SEQ * DH];
__device__ __nv_bfloat16 g_vth[(size_t)BH * NTILES * DH * KTILE];  // [bh][t][d][s]
__device__ __nv_bfloat16 g_vtl[(size_t)BH * NTILES * DH * KTILE];
__device__ float g_scratch[(size_t)BH * SEQ * SEQ];

// ---------------------------------------------------------------------------
__device__ __forceinline__ uint32_t packsplit(float x, float y, uint32_t& lo) {
    __nv_bfloat16 hx = __float2bfloat16_rn(x);
    __nv_bfloat16 hy = __float2bfloat16_rn(y);
    __nv_bfloat16 lx = __float2bfloat16_rn(x - __bfloat162float(hx));
    __nv_bfloat16 ly = __float2bfloat16_rn(y - __bfloat162float(hy));
    lo = (uint32_t)__bfloat16_as_ushort(lx) | ((uint32_t)__bfloat16_as_ushort(ly) << 16);
    return (uint32_t)__bfloat16_as_ushort(hx) | ((uint32_t)__bfloat16_as_ushort(hy) << 16);
}

__device__ __forceinline__ void mma16816(float* c, const uint32_t* a,
                                         uint32_t b0, uint32_t b1) {
    asm volatile(
        "mma.sync.aligned.m16n8k16.row.col.f32.bf16.bf16.f32 "
        "{%0,%1,%2,%3},{%4,%5,%6,%7},{%8,%9},{%0,%1,%2,%3};"
        : "+f"(c[0]), "+f"(c[1]), "+f"(c[2]), "+f"(c[3])
        : "r"(a[0]), "r"(a[1]), "r"(a[2]), "r"(a[3]), "r"(b0), "r"(b1));
}

__device__ __forceinline__ void ldsm4(uint32_t* r, uint32_t addr) {
    asm volatile("ldmatrix.sync.aligned.m8n8.x4.shared.b16 {%0,%1,%2,%3},[%4];"
                 : "=r"(r[0]), "=r"(r[1]), "=r"(r[2]), "=r"(r[3]) : "r"(addr));
}
__device__ __forceinline__ void ldsm2(uint32_t& r0, uint32_t& r1, uint32_t addr) {
    asm volatile("ldmatrix.sync.aligned.m8n8.x2.shared.b16 {%0,%1},[%2];"
                 : "=r"(r0), "=r"(r1) : "r"(addr));
}

__device__ __forceinline__ float epival(float s, int col, int qrow, const int* pads) {
    bool m = (pads[col] != 0) || (col > qrow);
    return m ? 0.f : __expf(s * 0.125f);
}

// ---- mbarrier + bulk-copy helpers -------------------------------------------
__device__ __forceinline__ void mbar_init(uint32_t a, uint32_t cnt) {
    asm volatile("mbarrier.init.shared.b64 [%0], %1;" :: "r"(a), "r"(cnt) : "memory");
}
__device__ __forceinline__ void mbar_expect(uint32_t a, uint32_t bytes) {
    asm volatile("mbarrier.arrive.expect_tx.shared.b64 _, [%0], %1;"
                 :: "r"(a), "r"(bytes) : "memory");
}
__device__ __forceinline__ void mbar_wait(uint32_t a, uint32_t phase) {
    asm volatile(
        "{\n\t.reg .pred P;\n"
        "WLOOP_%=:\n\t"
        "mbarrier.try_wait.parity.acquire.cta.shared::cta.b64 P, [%0], %1, 0x989680;\n\t"
        "@P bra WDONE_%=;\n\t"
        "bra WLOOP_%=;\n"
        "WDONE_%=:\n\t}"
        :: "r"(a), "r"(phase) : "memory");
}
__device__ __forceinline__ void bulk_g2s(uint32_t dst, const void* src,
                                         uint32_t bytes, uint32_t mbar) {
    asm volatile(
        "cp.async.bulk.shared::cta.global.mbarrier::complete_tx::bytes "
        "[%0], [%1], %2, [%3];"
        :: "r"(dst), "l"(src), "r"(bytes), "r"(mbar) : "memory");
}

// ---------------------------------------------------------------------------
// prep 1: K f32 -> bf16 hi/lo, tile-contiguous + SW swizzled (seg ^= row&7)
__global__ void split_k_kernel(const float* __restrict__ k) {
    int idx = blockIdx.x * 256 + threadIdx.x;            // one 16B segment each
    const float4* k2 = (const float4*)k;
    float4 fa = k2[idx * 2], fb = k2[idx * 2 + 1];
    uint32_t l0, l1, l2, l3;
    uint32_t h0 = packsplit(fa.x, fa.y, l0);
    uint32_t h1 = packsplit(fa.z, fa.w, l1);
    uint32_t h2 = packsplit(fb.x, fb.y, l2);
    uint32_t h3 = packsplit(fb.z, fb.w, l3);
    int row = idx >> 3, seg = idx & 7;
    int o = row * 8 + (seg ^ (row & 7));                 // uint4 index
    ((uint4*)g_kh)[o] = make_uint4(h0, h1, h2, h3);
    ((uint4*)g_kl)[o] = make_uint4(l0, l1, l2, l3);
}

// prep 2: V f32 [bh][s][d] -> V^T bf16 hi/lo, [bh][t][d][s128] swizzled
__global__ void vt_split_kernel(const float* __restrict__ v) {
    __shared__ float tile[32][33];
    const int bh = blockIdx.z;
    const int d0 = blockIdx.x * 32;
    const int s0 = blockIdx.y * 32;
    const float* vin = v + (size_t)bh * SEQ * DH;
    const int tx = threadIdx.x, ty = threadIdx.y;
#pragma unroll
    for (int j = 0; j < 32; j += 8)
        tile[ty + j][tx] = vin[(size_t)(s0 + ty + j) * DH + (d0 + tx)];
    __syncthreads();
#pragma unroll
    for (int j = 0; j < 32; j += 8) {
        float x = tile[tx][ty + j];
        __nv_bfloat16 h = __float2bfloat16_rn(x);
        __nv_bfloat16 l = __float2bfloat16_rn(x - __bfloat162float(h));
        int d = d0 + ty + j, s = s0 + tx;
        int t = s >> 7, sin = s & 127;
        int seg = (sin >> 3) ^ (d & 7);
        size_t o = ((size_t)(bh * NTILES + t) * DH + d) * KTILE + seg * 8 + (sin & 7);
        g_vth[o] = h;
        g_vtl[o] = l;
    }
}

// ---------------------------------------------------------------------------
__global__ __launch_bounds__(NTHREADS, 1)
void attn_mma_kernel(const float* __restrict__ q, const int* __restrict__ pad,
                     float* __restrict__ ctx, float* __restrict__ wout) {
    extern __shared__ char pool[];
    int*   pads = (int*)(pool + OFF_PAD);
    float* Lrow = (float*)(pool + OFF_L);
    float* Crow = (float*)(pool + OFF_C);
    int*   flg  = (int*)(pool + OFF_FLG);
    const uint32_t smem0 = (uint32_t)__cvta_generic_to_shared(pool);
    const uint32_t mbK = smem0 + OFF_MB, mbV = smem0 + OFF_MB + 8;

    const int tid  = threadIdx.x;
    const int wid  = tid >> 5;
    const int lane = tid & 31;
    const int r    = lane >> 2;
    const int tg   = lane & 3;
    const int xr   = lane & 7;          // swizzle xor for K/V LDSM rows
    const int sb   = (lane >> 3) & 1;
    const int wq   = wid >> 3;          // row block 0/1 (QK and PV)
    const int wn   = wid & 7;           // QK col block
    const int kp   = (wid >> 1) & 3;    // PV k-part (2 ks-chunks each)
    const int np   = wid & 1;           // PV n-part (32 dims)
    const int bh   = blockIdx.y;
    const int qbase = blockIdx.x * ROWS;
    const int b    = bh >> 4;

    const char* khb = (const char*)(g_kh + (size_t)bh * SEQ * DH);
    const char* klb = (const char*)(g_kl + (size_t)bh * SEQ * DH);
    const char* vhb = (const char*)(g_vth + (size_t)bh * NTILES * DH * KTILE);
    const char* vlb = (const char*)(g_vtl + (size_t)bh * NTILES * DH * KTILE);

    const int qk_tiles = (qbase + ROWS - 1) / KTILE + 1;

    // ---- init mbarriers, then kick K(0) ------------------------------------
    if (tid == 0) {
        mbar_init(mbK, 1);
        mbar_init(mbV, 1);
    }
    __syncthreads();
    if (tid == 0) {
        mbar_expect(mbK, 2 * SZ_KH);
        bulk_g2s(smem0 + OFF_K,          khb, SZ_KH, mbK);
        bulk_g2s(smem0 + OFF_K + SZ_KH,  klb, SZ_KH, mbK);
    }

    // ---- phase 0: zero P, loads --------------------------------------------
    {
        uint4 z = make_uint4(0, 0, 0, 0);
        for (int i = tid; i < ROWS * 256; i += NTHREADS) {       // 256 uint4/row
            int row = i >> 8, seg = i & 255;
            *(uint4*)(pool + OFF_P + row * PROWB + seg * 16) = z;
        }
        if (tid < ROWS) Lrow[tid] = 0.f;
        if (tid == 0) flg[0] = 0;
        const int* pg = pad + b * SEQ;
        for (int i = tid; i < SEQ; i += NTHREADS) pads[i] = pg[i];

        const float* qg = q + ((size_t)bh * SEQ + qbase) * DH;
        int row = tid >> 4, d4 = (tid & 15) * 4;
        float4 f = *(const float4*)&qg[row * DH + d4];
        uint32_t l0, l1;
        uint32_t h0 = packsplit(f.x, f.y, l0);
        uint32_t h1 = packsplit(f.z, f.w, l1);
        *(uint2*)(pool + OFF_QH + row * QROWB + d4 * 2) = make_uint2(h0, h1);
        *(uint2*)(pool + OFF_QL + row * QROWB + d4 * 2) = make_uint2(l0, l1);
    }
    __syncthreads();

    // ---- hoist Q a-fragments to registers ----------------------------------
    const uint32_t qA = smem0 + OFF_QH +
        (wq * 16 + (lane & 7) + ((lane >> 3) & 1) * 8) * QROWB + ((lane >> 4) & 1) * 16;
    uint32_t qa_h[4][4], qa_l[4][4];
#pragma unroll
    for (int ks = 0; ks < 4; ++ks) {
        ldsm4(qa_h[ks], qA + ks * 32);
        ldsm4(qa_l[ks], qA + ks * 32 + SZ_QROW);
    }

    // K/V/P LDSM lane bases (swizzled K/V: seg' = seg ^ xr)
    const int n0 = wn * 16;
    const uint32_t kBase = smem0 + OFF_K +
        (n0 + (lane & 7) + ((lane >> 4) & 1) * 8) * 128;
    const uint32_t vBase = smem0 + OFF_V + (np * 32 + (lane & 7)) * 256;
    const uint32_t pA = smem0 + OFF_P +
        (wq * 16 + (lane & 7) + ((lane >> 3) & 1) * 8) * PROWB + ((lane >> 4) & 1) * 16;

    const int pr0 = wq * 16 + r;
    const int qrow0 = qbase + pr0, qrow1 = qrow0 + 8;
    float lsum0 = 0.f, lsum1 = 0.f;
    float oc[4][4] = {};
    int kph = 0, vph = 0;

    // ---- fused QK+exp+PV tile loop ------------------------------------------
    for (int t = 0; t < qk_tiles; ++t) {
        // V(t) fill (bulk engine) overlaps QK(t) compute
        if (tid == 0) {
            mbar_expect(mbV, 2 * SZ_VH);
            bulk_g2s(smem0 + OFF_V,         vhb + (size_t)t * SZ_VH, SZ_VH, mbV);
            bulk_g2s(smem0 + OFF_V + SZ_VH, vlb + (size_t)t * SZ_VH, SZ_VH, mbV);
        }
        mbar_wait(mbK, kph); kph ^= 1;     // K(t) ready

        // QK^T + exp -> P(t)
        float c0[4] = {0, 0, 0, 0}, c1[4] = {0, 0, 0, 0};
#pragma unroll
        for (int ks = 0; ks < 4; ++ks) {
            uint32_t koff = (uint32_t)(((2 * ks + sb) ^ xr) << 4);
            uint32_t kh[4], kl[4];
            ldsm4(kh, kBase + koff);
            ldsm4(kl, kBase + koff + SZ_KH);
            mma16816(c0, qa_h[ks], kh[0], kh[1]);
            mma16816(c0, qa_h[ks], kl[0], kl[1]);
            mma16816(c0, qa_l[ks], kh[0], kh[1]);
            mma16816(c1, qa_h[ks], kh[2], kh[3]);
            mma16816(c1, qa_h[ks], kl[2], kl[3]);
            mma16816(c1, qa_l[ks], kh[2], kh[3]);
        }
        int colb = t * KTILE + n0 + tg * 2;
#pragma unroll
        for (int nt = 0; nt < 2; ++nt) {
            float* cc = nt ? c1 : c0;
            int cb = colb + nt * 8;
            float e0 = epival(cc[0], cb,     qrow0, pads);
            float e1 = epival(cc[1], cb + 1, qrow0, pads);
            float e2 = epival(cc[2], cb,     qrow1, pads);
            float e3 = epival(cc[3], cb + 1, qrow1, pads);
            uint32_t lo01, lo23;
            uint32_t hi01 = packsplit(e0, e1, lo01);
            uint32_t hi23 = packsplit(e2, e3, lo23);
            char* b0p = pool + OFF_P + pr0 * PROWB + cb * 2;
            char* b1p = pool + OFF_P + (pr0 + 8) * PROWB + cb * 2;
            *(uint32_t*)(b0p)        = hi01;
            *(uint32_t*)(b0p + 2048) = lo01;
            *(uint32_t*)(b1p)        = hi23;
            *(uint32_t*)(b1p + 2048) = lo23;
            lsum0 += e0 + e1;
            lsum1 += e2 + e3;
        }
        __syncthreads();       // P(t) visible; all QK reads of K done

        // K(t+1) fill overlaps PV(t)
        if (t + 1 < qk_tiles && tid == 0) {
            mbar_expect(mbK, 2 * SZ_KH);
            bulk_g2s(smem0 + OFF_K,         khb + (size_t)(t + 1) * SZ_KH, SZ_KH, mbK);
            bulk_g2s(smem0 + OFF_K + SZ_KH, klb + (size_t)(t + 1) * SZ_KH, SZ_KH, mbK);
        }
        mbar_wait(mbV, vph); vph ^= 1;     // V(t) ready

        // PV(t)
#pragma unroll
        for (int kk = 0; kk < 2; ++kk) {
            int ks = kp * 2 + kk;
            uint32_t voff = (uint32_t)(((2 * ks + sb) ^ xr) << 4);
            uint32_t ah[4], al[4];
            ldsm4(ah, pA + t * 256 + ks * 32);
            ldsm4(al, pA + t * 256 + ks * 32 + 2048);
#pragma unroll
            for (int nb = 0; nb < 4; ++nb) {
                uint32_t bh0, bh1, bl0, bl1;
                ldsm2(bh0, bh1, vBase + nb * 2048 + voff);
                ldsm2(bl0, bl1, vBase + nb * 2048 + voff + SZ_VH);
                mma16816(oc[nb], ah, bh0, bh1);
                mma16816(oc[nb], ah, bl0, bl1);
                mma16816(oc[nb], al, bh0, bh1);
            }
        }
        __syncthreads();       // V read done -> next V fill safe
    }

    // ---- Lrow reduction -------------------------------------------------------
    lsum0 += __shfl_xor_sync(0xffffffffu, lsum0, 1);
    lsum0 += __shfl_xor_sync(0xffffffffu, lsum0, 2);
    lsum1 += __shfl_xor_sync(0xffffffffu, lsum1, 1);
    lsum1 += __shfl_xor_sync(0xffffffffu, lsum1, 2);
    if (tg == 0) {
        atomicAdd(&Lrow[pr0], lsum0);
        atomicAdd(&Lrow[pr0 + 8], lsum1);
    }
    __syncthreads();

    // ---- phase 2a: degenerate detection ----------------------------------------
    {
        int row = tid >> 4, ch = tid & 15;
        int qrow = qbase + row;
        int cnt = 0;
        for (int kx = ch * 64; kx < ch * 64 + 64; ++kx) {
            bool pd = pads[kx] != 0;
            cnt += ((kx <= qrow) ? pd : !pd) ? 1 : 0;
        }
        cnt += __shfl_xor_sync(0xffffffffu, cnt, 1);
        cnt += __shfl_xor_sync(0xffffffffu, cnt, 2);
        cnt += __shfl_xor_sync(0xffffffffu, cnt, 4);
        cnt += __shfl_xor_sync(0xffffffffu, cnt, 8);
        if (ch == 0) {
            Crow[row] = (float)cnt;
            if (Lrow[row] == 0.f) flg[0] = 1;
        }
    }
    __syncthreads();

    // ---- phase 2b: reconstruct+normalize -> smem stage -> bulk store ------------
    {
        const int rloc = tid >> 6;          // 0..7 row within chunk
        const int cidx = tid & 63;          // 64 threads per row
        float* wbase = wout + ((size_t)bh * SEQ + qbase) * SEQ;
#pragma unroll
        for (int g = 0; g < 4; ++g) {
            const uint32_t sbuf = smem0 + OFF_K + (g & 1) * 32768;
            if (g >= 2) {
                if (tid == 0)
                    asm volatile("cp.async.bulk.wait_group.read 1;" ::: "memory");
                __syncthreads();             // buffer (g&1) reusable
            }
            const int row = g * 8 + rloc;
            const int qrow = qbase + row;
            const float l = Lrow[row];
            const bool degen = (l == 0.f);
            const float inv  = 1.f / l;
            const float fill = 1.f / Crow[row];
            char* prow = pool + OFF_P + row * PROWB;
#pragma unroll
            for (int j = 0; j < 4; ++j) {
                int col = j * 256 + cidx * 4;
                uint2 hh = *(uint2*)(prow + col * 2);
                uint2 ll = *(uint2*)(prow + 2048 + col * 2);
                float2 fh01 = __bfloat1622float2(*(__nv_bfloat162*)&hh.x);
                float2 fh23 = __bfloat1622float2(*(__nv_bfloat162*)&hh.y);
                float2 fl01 = __bfloat1622float2(*(__nv_bfloat162*)&ll.x);
                float2 fl23 = __bfloat1622float2(*(__nv_bfloat162*)&ll.y);
                float w[4] = {fh01.x + fl01.x, fh01.y + fl01.y,
                              fh23.x + fl23.x, fh23.y + fl23.y};
                if (degen) {
#pragma unroll
                    for (int u = 0; u < 4; ++u) {
                        int kx = col + u;
                        bool pd = pads[kx] != 0;
                        w[u] = ((kx <= qrow) ? pd : !pd) ? fill : 0.f;
                    }
                    uint32_t L01, L23;
                    uint32_t H01 = packsplit(w[0], w[1], L01);
                    uint32_t H23 = packsplit(w[2], w[3], L23);
                    *(uint2*)(prow + col * 2)        = make_uint2(H01, H23);
                    *(uint2*)(prow + 2048 + col * 2) = make_uint2(L01, L23);
                } else {
#pragma unroll
                    for (int u = 0; u < 4; ++u) w[u] *= inv;
                }
                uint32_t saddr = sbuf + rloc * 4096 + col * 4;
                asm volatile("st.shared.v4.f32 [%0],{%1,%2,%3,%4};"
                             :: "r"(saddr), "f"(w[0]), "f"(w[1]),
                                "f"(w[2]), "f"(w[3]));
            }
            __syncthreads();                 // chunk staged
            if (tid == 0) {
                asm volatile("fence.proxy.async.shared::cta;" ::: "memory");
                asm volatile(
                    "cp.async.bulk.global.shared::cta.bulk_group [%0], [%1], %2;"
                    :: "l"(wbase + g * 8192), "r"(sbuf), "r"(32768) : "memory");
                asm volatile("cp.async.bulk.commit_group;" ::: "memory");
            }
        }
        if (tid == 0)
            asm volatile("cp.async.bulk.wait_group.read 0;" ::: "memory");
        __syncthreads();                     // stage area (incl. V buf) free
    }

    // ---- degenerate fallback: recompute PV over all tiles from stored P --------
    if (flg[0]) {
#pragma unroll
        for (int nb = 0; nb < 4; ++nb)
#pragma unroll
            for (int i = 0; i < 4; ++i) oc[nb][i] = 0.f;
        for (int t = 0; t < NTILES; ++t) {
            if (tid == 0) {
                mbar_expect(mbV, 2 * SZ_VH);
                bulk_g2s(smem0 + OFF_V,         vhb + (size_t)t * SZ_VH, SZ_VH, mbV);
                bulk_g2s(smem0 + OFF_V + SZ_VH, vlb + (size_t)t * SZ_VH, SZ_VH, mbV);
            }
            mbar_wait(mbV, vph); vph ^= 1;
#pragma unroll
            for (int kk = 0; kk < 2; ++kk) {
                int ks = kp * 2 + kk;
                uint32_t voff = (uint32_t)(((2 * ks + sb) ^ xr) << 4);
                uint32_t ah[4], al[4];
                ldsm4(ah, pA + t * 256 + ks * 32);
                ldsm4(al, pA + t * 256 + ks * 32 + 2048);
#pragma unroll
                for (int nb = 0; nb < 4; ++nb) {
                    uint32_t bh0, bh1, bl0, bl1;
                    ldsm2(bh0, bh1, vBase + nb * 2048 + voff);
                    ldsm2(bl0, bl1, vBase + nb * 2048 + voff + SZ_VH);
                    mma16816(oc[nb], ah, bh0, bh1);
                    mma16816(oc[nb], ah, bl0, bl1);
                    mma16816(oc[nb], al, bh0, bh1);
                }
            }
            __syncthreads();
        }
    }

    // ---- cross-warp k-part reduction + scaled epilogue --------------------------
    {
        char* base = pool + OFF_P + kp * 8192 + (wq * 2 + np) * 2048 + lane * 4;
#pragma unroll
        for (int nb = 0; nb < 4; ++nb)
#pragma unroll
            for (int i = 0; i < 4; ++i)
                *(float*)(base + (nb * 4 + i) * 128) = oc[nb][i];
    }
    __syncthreads();
    {
        int l = tid & 31, g = tid >> 7, vset = (tid >> 5) & 3;
        int rr = l >> 2, tg4 = l & 3;
        int dim0 = (g & 1) * 32 + vset * 8 + tg4 * 2;
        int rowa = (g >> 1) * 16 + rr;
        int rowb = rowa + 8;
        float acc[4] = {0.f, 0.f, 0.f, 0.f};
#pragma unroll
        for (int kpp = 0; kpp < 4; ++kpp) {
            char* bp = pool + OFF_P + kpp * 8192 + g * 2048 + l * 4;
#pragma unroll
            for (int i = 0; i < 4; ++i)
                acc[i] += *(float*)(bp + (vset * 4 + i) * 128);
        }
        float la = Lrow[rowa], lb = Lrow[rowb];
        float sa = (la == 0.f) ? 1.f : 1.f / la;
        float sb2 = (lb == 0.f) ? 1.f : 1.f / lb;
        float* crow = ctx + ((size_t)bh * SEQ + qbase) * DH;
        *(float2*)&crow[rowa * DH + dim0] = make_float2(acc[0] * sa, acc[1] * sa);
        *(float2*)&crow[rowb * DH + dim0] = make_float2(acc[2] * sb2, acc[3] * sb2);
    }
}

// ---------------------------------------------------------------------------
extern "C" void kernel_launch(void* const* d_in, const int* in_sizes, int n_in,
                              void* d_out, int out_size) {
    (void)in_sizes; (void)n_in;
    const float* q   = (const float*)d_in[0];
    const float* k   = (const float*)d_in[1];
    const float* v   = (const float*)d_in[2];
    const int*   pad = (const int*)d_in[3];

    const long long CTXN = (long long)BH * SEQ * DH;
    const long long WN   = (long long)BH * SEQ * SEQ;

    float* ctxp;
    float* wp;
    if ((long long)out_size >= CTXN + WN) {
        ctxp = (float*)d_out;
        wp   = (float*)d_out + CTXN;
    } else if ((long long)out_size == WN) {
        void* s = nullptr;
        cudaGetSymbolAddress(&s, g_scratch);
        ctxp = (float*)s;
        wp   = (float*)d_out;
    } else {
        void* s = nullptr;
        cudaGetSymbolAddress(&s, g_scratch);
        ctxp = (float*)d_out;
        wp   = (float*)s;
    }

    static bool attr_done = false;
    if (!attr_done) {
        cudaFuncSetAttribute(attn_mma_kernel,
                             cudaFuncAttributeMaxDynamicSharedMemorySize,
                             SMEM_BYTES);
        attr_done = true;
    }

    split_k_kernel<<<(BH * SEQ * DH / 8 + 255) / 256, 256>>>(k);
    dim3 gt(DH / 32, SEQ / 32, BH), bt(32, 8);
    vt_split_kernel<<<gt, bt>>>(v);

    dim3 ga(SEQ / ROWS, BH), ba(NTHREADS);
    attn_mma_kernel<<<ga, ba, SMEM_BYTES>>>(q, pad, ctxp, wp);
}

// round 10
// speedup vs baseline: 7.9995x; 1.0104x over previous
#include <cuda_runtime.h>
#include <cuda_bf16.h>
#include <cstdint>

#define BH        64
#define SEQ       1024
#define DH        64
#define ROWS      16
#define NTHREADS  256
#define KTILE     128
#define NTILES    8
#define QROWB     144               // Q smem row bytes (64 bf16 + pad)
#define SZ_KH     16384             // K hi sub-buffer (128 rows x 128B, swizzled)
#define SZ_VH     16384             // V hi sub-buffer (64 rows x 256B, swizzled)

// smem byte offsets (NO P buffer -> 74.4KB -> 2 CTAs/SM)
#define OFF_K    0                  // K hi 16K | lo 16K
#define OFF_V    32768              // V hi 16K | lo 16K
#define OFF_QH   65536
#define SZ_QROW  (ROWS * QROWB)     // 2304
#define OFF_QL   (OFF_QH + SZ_QROW) // 67840
#define OFF_PAD  (OFF_QL + SZ_QROW) // 70144
#define OFF_L    (OFF_PAD + SEQ*4)  // 74240
#define OFF_C    (OFF_L + ROWS*4)   // 74304
#define OFF_FLG  (OFF_C + ROWS*4)   // 74368
#define OFF_MB   (OFF_FLG + 16)     // 74384 (mbK, mbV)
#define SMEM_BYTES (OFF_MB + 16)    // 74400  (x2 = 148.8K <= 227K)

__device__ __nv_bfloat16 g_kh[(size_t)BH * SEQ * DH];   // tile-contig, swizzled
__device__ __nv_bfloat16 g_kl[(size_t)BH * SEQ * DH];
__device__ __nv_bfloat16 g_vth[(size_t)BH * NTILES * DH * KTILE];  // [bh][t][d][s]
__device__ __nv_bfloat16 g_vtl[(size_t)BH * NTILES * DH * KTILE];
__device__ float g_scratch[(size_t)BH * SEQ * SEQ];

// ---------------------------------------------------------------------------
__device__ __forceinline__ uint32_t packsplit(float x, float y, uint32_t& lo) {
    __nv_bfloat16 hx = __float2bfloat16_rn(x);
    __nv_bfloat16 hy = __float2bfloat16_rn(y);
    __nv_bfloat16 lx = __float2bfloat16_rn(x - __bfloat162float(hx));
    __nv_bfloat16 ly = __float2bfloat16_rn(y - __bfloat162float(hy));
    lo = (uint32_t)__bfloat16_as_ushort(lx) | ((uint32_t)__bfloat16_as_ushort(ly) << 16);
    return (uint32_t)__bfloat16_as_ushort(hx) | ((uint32_t)__bfloat16_as_ushort(hy) << 16);
}

__device__ __forceinline__ void mma16816(float* c, const uint32_t* a,
                                         uint32_t b0, uint32_t b1) {
    asm volatile(
        "mma.sync.aligned.m16n8k16.row.col.f32.bf16.bf16.f32 "
        "{%0,%1,%2,%3},{%4,%5,%6,%7},{%8,%9},{%0,%1,%2,%3};"
        : "+f"(c[0]), "+f"(c[1]), "+f"(c[2]), "+f"(c[3])
        : "r"(a[0]), "r"(a[1]), "r"(a[2]), "r"(a[3]), "r"(b0), "r"(b1));
}

__device__ __forceinline__ void ldsm4(uint32_t* r, uint32_t addr) {
    asm volatile("ldmatrix.sync.aligned.m8n8.x4.shared.b16 {%0,%1,%2,%3},[%4];"
                 : "=r"(r[0]), "=r"(r[1]), "=r"(r[2]), "=r"(r[3]) : "r"(addr));
}
__device__ __forceinline__ void ldsm2(uint32_t& r0, uint32_t& r1, uint32_t addr) {
    asm volatile("ldmatrix.sync.aligned.m8n8.x2.shared.b16 {%0,%1},[%2];"
                 : "=r"(r0), "=r"(r1) : "r"(addr));
}

__device__ __forceinline__ float epival(float s, int col, int qrow, const int* pads) {
    bool m = (pads[col] != 0) || (col > qrow);
    return m ? 0.f : __expf(s * 0.125f);
}

// ---- mbarrier + bulk-copy helpers -------------------------------------------
__device__ __forceinline__ void mbar_init(uint32_t a, uint32_t cnt) {
    asm volatile("mbarrier.init.shared.b64 [%0], %1;" :: "r"(a), "r"(cnt) : "memory");
}
__device__ __forceinline__ void mbar_expect(uint32_t a, uint32_t bytes) {
    asm volatile("mbarrier.arrive.expect_tx.shared.b64 _, [%0], %1;"
                 :: "r"(a), "r"(bytes) : "memory");
}
__device__ __forceinline__ void mbar_wait(uint32_t a, uint32_t phase) {
    asm volatile(
        "{\n\t.reg .pred P;\n"
        "WLOOP_%=:\n\t"
        "mbarrier.try_wait.parity.acquire.cta.shared::cta.b64 P, [%0], %1, 0x989680;\n\t"
        "@P bra WDONE_%=;\n\t"
        "bra WLOOP_%=;\n"
        "WDONE_%=:\n\t}"
        :: "r"(a), "r"(phase) : "memory");
}
__device__ __forceinline__ void bulk_g2s(uint32_t dst, const void* src,
                                         uint32_t bytes, uint32_t mbar) {
    asm volatile(
        "cp.async.bulk.shared::cta.global.mbarrier::complete_tx::bytes "
        "[%0], [%1], %2, [%3];"
        :: "r"(dst), "l"(src), "r"(bytes), "r"(mbar) : "memory");
}

// ---------------------------------------------------------------------------
// prep 1: K f32 -> bf16 hi/lo, tile-contiguous + swizzled (seg ^= row&7)
__global__ void split_k_kernel(const float* __restrict__ k) {
    int idx = blockIdx.x * 256 + threadIdx.x;            // one 16B segment each
    const float4* k2 = (const float4*)k;
    float4 fa = k2[idx * 2], fb = k2[idx * 2 + 1];
    uint32_t l0, l1, l2, l3;
    uint32_t h0 = packsplit(fa.x, fa.y, l0);
    uint32_t h1 = packsplit(fa.z, fa.w, l1);
    uint32_t h2 = packsplit(fb.x, fb.y, l2);
    uint32_t h3 = packsplit(fb.z, fb.w, l3);
    int row = idx >> 3, seg = idx & 7;
    int o = row * 8 + (seg ^ (row & 7));                 // uint4 index
    ((uint4*)g_kh)[o] = make_uint4(h0, h1, h2, h3);
    ((uint4*)g_kl)[o] = make_uint4(l0, l1, l2, l3);
}

// prep 2: V f32 [bh][s][d] -> V^T bf16 hi/lo, [bh][t][d][s128] swizzled
__global__ void vt_split_kernel(const float* __restrict__ v) {
    __shared__ float tile[32][33];
    const int bh = blockIdx.z;
    const int d0 = blockIdx.x * 32;
    const int s0 = blockIdx.y * 32;
    const float* vin = v + (size_t)bh * SEQ * DH;
    const int tx = threadIdx.x, ty = threadIdx.y;
#pragma unroll
    for (int j = 0; j < 32; j += 8)
        tile[ty + j][tx] = vin[(size_t)(s0 + ty + j) * DH + (d0 + tx)];
    __syncthreads();
#pragma unroll
    for (int j = 0; j < 32; j += 8) {
        float x = tile[tx][ty + j];
        __nv_bfloat16 h = __float2bfloat16_rn(x);
        __nv_bfloat16 l = __float2bfloat16_rn(x - __bfloat162float(h));
        int d = d0 + ty + j, s = s0 + tx;
        int t = s >> 7, sin = s & 127;
        int seg = (sin >> 3) ^ (d & 7);
        size_t o = ((size_t)(bh * NTILES + t) * DH + d) * KTILE + seg * 8 + (sin & 7);
        g_vth[o] = h;
        g_vtl[o] = l;
    }
}

// ---------------------------------------------------------------------------
// Two-pass, P-free attention. Pass 1: QK+exp -> row sums. Pass 2: recompute
// QK+exp, normalize immediately, STG W, PV directly from register A-frags.
__global__ __launch_bounds__(NTHREADS, 2)
void attn_mma_kernel(const float* __restrict__ q, const int* __restrict__ pad,
                     float* __restrict__ ctx, float* __restrict__ wout) {
    extern __shared__ char pool[];
    int*   pads = (int*)(pool + OFF_PAD);
    float* Lrow = (float*)(pool + OFF_L);
    float* Crow = (float*)(pool + OFF_C);
    int*   flg  = (int*)(pool + OFF_FLG);
    const uint32_t smem0 = (uint32_t)__cvta_generic_to_shared(pool);
    const uint32_t mbK = smem0 + OFF_MB, mbV = smem0 + OFF_MB + 8;

    const int tid  = threadIdx.x;
    const int wid  = tid >> 5;          // 0..7: warp's 16-col k-chunk
    const int lane = tid & 31;
    const int r    = lane >> 2;
    const int tg   = lane & 3;
    const int xr   = lane & 7;          // swizzle xor
    const int sb   = (lane >> 3) & 1;
    const int bh   = blockIdx.y;
    const int qbase = blockIdx.x * ROWS;
    const int b    = bh >> 4;

    const char* khb = (const char*)(g_kh + (size_t)bh * SEQ * DH);
    const char* klb = (const char*)(g_kl + (size_t)bh * SEQ * DH);
    const char* vhb = (const char*)(g_vth + (size_t)bh * NTILES * DH * KTILE);
    const char* vlb = (const char*)(g_vtl + (size_t)bh * NTILES * DH * KTILE);

    const int T = (qbase + ROWS - 1) / KTILE + 1;   // causal tile count

    if (tid == 0) {
        mbar_init(mbK, 1);
        mbar_init(mbV, 1);
    }
    __syncthreads();
    if (tid == 0) {
        mbar_expect(mbK, 2 * SZ_KH);
        bulk_g2s(smem0 + OFF_K,          khb, SZ_KH, mbK);
        bulk_g2s(smem0 + OFF_K + SZ_KH,  klb, SZ_KH, mbK);
        mbar_expect(mbV, 2 * SZ_VH);
        bulk_g2s(smem0 + OFF_V,          vhb, SZ_VH, mbV);
        bulk_g2s(smem0 + OFF_V + SZ_VH,  vlb, SZ_VH, mbV);
    }

    // ---- phase 0: pads, Lrow, Q load+split ---------------------------------
    {
        if (tid < ROWS) Lrow[tid] = 0.f;
        if (tid == 0) flg[0] = 0;
        const int* pg = pad + b * SEQ;
#pragma unroll
        for (int i = 0; i < 4; ++i) pads[tid + i * NTHREADS] = pg[tid + i * NTHREADS];

        const float* qg = q + ((size_t)bh * SEQ + qbase) * DH;
        int row = tid >> 4, d4 = (tid & 15) * 4;     // 256 thr = 16x16 exactly
        float4 f = *(const float4*)&qg[row * DH + d4];
        uint32_t l0, l1;
        uint32_t h0 = packsplit(f.x, f.y, l0);
        uint32_t h1 = packsplit(f.z, f.w, l1);
        *(uint2*)(pool + OFF_QH + row * QROWB + d4 * 2) = make_uint2(h0, h1);
        *(uint2*)(pool + OFF_QL + row * QROWB + d4 * 2) = make_uint2(l0, l1);
    }
    __syncthreads();

    // ---- Crow (degenerate fill counts; pads-only, compute early) -----------
    {
        int row = tid >> 4, ch = tid & 15;
        int qrow = qbase + row;
        int cnt = 0;
        for (int kx = ch * 64; kx < ch * 64 + 64; ++kx) {
            bool pd = pads[kx] != 0;
            cnt += ((kx <= qrow) ? pd : !pd) ? 1 : 0;
        }
        cnt += __shfl_xor_sync(0xffffffffu, cnt, 1);
        cnt += __shfl_xor_sync(0xffffffffu, cnt, 2);
        cnt += __shfl_xor_sync(0xffffffffu, cnt, 4);
        cnt += __shfl_xor_sync(0xffffffffu, cnt, 8);
        if (ch == 0) Crow[row] = (float)cnt;
    }

    // ---- hoist Q a-fragments -------------------------------------------------
    const uint32_t qA = smem0 + OFF_QH +
        ((lane & 7) + ((lane >> 3) & 1) * 8) * QROWB + ((lane >> 4) & 1) * 16;
    uint32_t qa_h[4][4], qa_l[4][4];
#pragma unroll
    for (int ks = 0; ks < 4; ++ks) {
        ldsm4(qa_h[ks], qA + ks * 32);
        ldsm4(qa_l[ks], qA + ks * 32 + SZ_QROW);
    }

    const int n0 = wid * 16;
    const uint32_t kBase = smem0 + OFF_K +
        (n0 + (lane & 7) + ((lane >> 4) & 1) * 8) * 128;
    const uint32_t vBase = smem0 + OFF_V + (lane & 7) * 256;
    const uint32_t voff = (uint32_t)(((2 * wid + sb) ^ xr) << 4);

    const int qrow0 = qbase + r, qrow1 = qrow0 + 8;
    float lsum0 = 0.f, lsum1 = 0.f;
    int kph = 0, vph = 0;

    // ======== PASS 1: row sums =================================================
    for (int t = 0; t < T; ++t) {
        mbar_wait(mbK, kph); kph ^= 1;

        float c0[4] = {0, 0, 0, 0}, c1[4] = {0, 0, 0, 0};
#pragma unroll
        for (int ks = 0; ks < 4; ++ks) {
            uint32_t koff = (uint32_t)(((2 * ks + sb) ^ xr) << 4);
            uint32_t kh[4], kl[4];
            ldsm4(kh, kBase + koff);
            ldsm4(kl, kBase + koff + SZ_KH);
            mma16816(c0, qa_h[ks], kh[0], kh[1]);
            mma16816(c0, qa_h[ks], kl[0], kl[1]);
            mma16816(c0, qa_l[ks], kh[0], kh[1]);
            mma16816(c1, qa_h[ks], kh[2], kh[3]);
            mma16816(c1, qa_h[ks], kl[2], kl[3]);
            mma16816(c1, qa_l[ks], kh[2], kh[3]);
        }
        int colb = t * KTILE + n0 + tg * 2;
#pragma unroll
        for (int nt = 0; nt < 2; ++nt) {
            float* cc = nt ? c1 : c0;
            int cb = colb + nt * 8;
            lsum0 += epival(cc[0], cb,     qrow0, pads)
                   + epival(cc[1], cb + 1, qrow0, pads);
            lsum1 += epival(cc[2], cb,     qrow1, pads)
                   + epival(cc[3], cb + 1, qrow1, pads);
        }
        __syncthreads();                 // K reads done
        if (tid == 0) {                  // refill: next pass-1 tile, or K(0) for pass 2
            int tile = (t + 1 < T) ? t + 1 : 0;
            mbar_expect(mbK, 2 * SZ_KH);
            bulk_g2s(smem0 + OFF_K,         khb + (size_t)tile * SZ_KH, SZ_KH, mbK);
            bulk_g2s(smem0 + OFF_K + SZ_KH, klb + (size_t)tile * SZ_KH, SZ_KH, mbK);
        }
    }

    // ---- Lrow reduction + degenerate flag -------------------------------------
    lsum0 += __shfl_xor_sync(0xffffffffu, lsum0, 1);
    lsum0 += __shfl_xor_sync(0xffffffffu, lsum0, 2);
    lsum1 += __shfl_xor_sync(0xffffffffu, lsum1, 1);
    lsum1 += __shfl_xor_sync(0xffffffffu, lsum1, 2);
    if (tg == 0) {
        atomicAdd(&Lrow[r], lsum0);
        atomicAdd(&Lrow[r + 8], lsum1);
    }
    __syncthreads();
    if (tid < ROWS && Lrow[tid] == 0.f) flg[0] = 1;
    __syncthreads();
    const int T2 = flg[0] ? NTILES : T;

    // per-row normalization params (hoisted)
    const float l0 = Lrow[r], l1 = Lrow[r + 8];
    const bool  dg0 = (l0 == 0.f), dg1 = (l1 == 0.f);
    const float inv0 = 1.f / l0, inv1 = 1.f / l1;
    const float fl0 = 1.f / Crow[r], fl1 = 1.f / Crow[r + 8];

    // zero-fill W columns beyond the causal tiles (only when no degen rows)
    if (!flg[0]) {
        float4 z = make_float4(0.f, 0.f, 0.f, 0.f);
        for (int tt = T; tt < NTILES; ++tt)
#pragma unroll 2
            for (int j = tid; j < 512; j += NTHREADS) {
                int row = j >> 5, seg = j & 31;
                *(float4*)&wout[((size_t)bh * SEQ + qbase + row) * SEQ
                                + tt * KTILE + seg * 4] = z;
            }
    }

    float oc[8][4] = {};
    float* wr0 = wout + ((size_t)bh * SEQ + qrow0) * SEQ;
    float* wr1 = wout + ((size_t)bh * SEQ + qrow1) * SEQ;

    // ======== PASS 2: recompute, normalize, store W, PV from registers =========
    for (int t = 0; t < T2; ++t) {
        mbar_wait(mbK, kph); kph ^= 1;

        float c0[4] = {0, 0, 0, 0}, c1[4] = {0, 0, 0, 0};
#pragma unroll
        for (int ks = 0; ks < 4; ++ks) {
            uint32_t koff = (uint32_t)(((2 * ks + sb) ^ xr) << 4);
            uint32_t kh[4], kl[4];
            ldsm4(kh, kBase + koff);
            ldsm4(kl, kBase + koff + SZ_KH);
            mma16816(c0, qa_h[ks], kh[0], kh[1]);
            mma16816(c0, qa_h[ks], kl[0], kl[1]);
            mma16816(c0, qa_l[ks], kh[0], kh[1]);
            mma16816(c1, qa_h[ks], kh[2], kh[3]);
            mma16816(c1, qa_h[ks], kl[2], kl[3]);
            mma16816(c1, qa_l[ks], kh[2], kh[3]);
        }

        uint32_t ah[4], al[4];
        int colb = t * KTILE + n0 + tg * 2;
#pragma unroll
        for (int nt = 0; nt < 2; ++nt) {
            float* cc = nt ? c1 : c0;
            int cb = colb + nt * 8;
            float e0 = epival(cc[0], cb,     qrow0, pads);
            float e1 = epival(cc[1], cb + 1, qrow0, pads);
            float e2 = epival(cc[2], cb,     qrow1, pads);
            float e3 = epival(cc[3], cb + 1, qrow1, pads);
            float w0, w1, w2, w3;
            if (dg0) {
                bool p0 = pads[cb] != 0, p1 = pads[cb + 1] != 0;
                w0 = ((cb     <= qrow0) ? p0 : !p0) ? fl0 : 0.f;
                w1 = ((cb + 1 <= qrow0) ? p1 : !p1) ? fl0 : 0.f;
            } else { w0 = e0 * inv0; w1 = e1 * inv0; }
            if (dg1) {
                bool p0 = pads[cb] != 0, p1 = pads[cb + 1] != 0;
                w2 = ((cb     <= qrow1) ? p0 : !p0) ? fl1 : 0.f;
                w3 = ((cb + 1 <= qrow1) ? p1 : !p1) ? fl1 : 0.f;
            } else { w2 = e2 * inv1; w3 = e3 * inv1; }
            *(float2*)&wr0[cb] = make_float2(w0, w1);
            *(float2*)&wr1[cb] = make_float2(w2, w3);
            ah[nt * 2]     = packsplit(w0, w1, al[nt * 2]);
            ah[nt * 2 + 1] = packsplit(w2, w3, al[nt * 2 + 1]);
        }
        __syncthreads();                 // K reads done
        if (tid == 0 && t + 1 < T2) {
            mbar_expect(mbK, 2 * SZ_KH);
            bulk_g2s(smem0 + OFF_K,         khb + (size_t)(t + 1) * SZ_KH, SZ_KH, mbK);
            bulk_g2s(smem0 + OFF_K + SZ_KH, klb + (size_t)(t + 1) * SZ_KH, SZ_KH, mbK);
        }

        mbar_wait(mbV, vph); vph ^= 1;
#pragma unroll
        for (int nb = 0; nb < 8; ++nb) {
            uint32_t bh0, bh1, bl0, bl1;
            ldsm2(bh0, bh1, vBase + nb * 2048 + voff);
            ldsm2(bl0, bl1, vBase + nb * 2048 + voff + SZ_VH);
            mma16816(oc[nb], ah, bh0, bh1);
            mma16816(oc[nb], ah, bl0, bl1);
            mma16816(oc[nb], al, bh0, bh1);
        }
        __syncthreads();                 // V reads done
        if (tid == 0 && t + 1 < T2) {
            mbar_expect(mbV, 2 * SZ_VH);
            bulk_g2s(smem0 + OFF_V,         vhb + (size_t)(t + 1) * SZ_VH, SZ_VH, mbV);
            bulk_g2s(smem0 + OFF_V + SZ_VH, vlb + (size_t)(t + 1) * SZ_VH, SZ_VH, mbV);
        }
    }

    // ---- cross-warp k-chunk reduction (K area is free now) --------------------
    {
        char* base = pool + OFF_K + wid * 4096 + lane * 4;
#pragma unroll
        for (int nb = 0; nb < 8; ++nb)
#pragma unroll
            for (int i = 0; i < 4; ++i)
                *(float*)(base + (nb * 4 + i) * 128) = oc[nb][i];
    }
    __syncthreads();
    {
        int vset = tid >> 5;                        // 0..7 -> dim block
        float acc[4] = {0.f, 0.f, 0.f, 0.f};
#pragma unroll
        for (int ww = 0; ww < 8; ++ww) {
            char* bp = pool + OFF_K + ww * 4096 + lane * 4;
#pragma unroll
            for (int i = 0; i < 4; ++i)
                acc[i] += *(float*)(bp + (vset * 4 + i) * 128);
        }
        int rowa = lane >> 2;
        int dim0 = vset * 8 + (lane & 3) * 2;
        float* crow = ctx + ((size_t)bh * SEQ + qbase) * DH;
        *(float2*)&crow[rowa * DH + dim0]       = make_float2(acc[0], acc[1]);
        *(float2*)&crow[(rowa + 8) * DH + dim0] = make_float2(acc[2], acc[3]);
    }
}

// ---------------------------------------------------------------------------
extern "C" void kernel_launch(void* const* d_in, const int* in_sizes, int n_in,
                              void* d_out, int out_size) {
    (void)in_sizes; (void)n_in;
    const float* q   = (const float*)d_in[0];
    const float* k   = (const float*)d_in[1];
    const float* v   = (const float*)d_in[2];
    const int*   pad = (const int*)d_in[3];

    const long long CTXN = (long long)BH * SEQ * DH;
    const long long WN   = (long long)BH * SEQ * SEQ;

    float* ctxp;
    float* wp;
    if ((long long)out_size >= CTXN + WN) {
        ctxp = (float*)d_out;
        wp   = (float*)d_out + CTXN;
    } else if ((long long)out_size == WN) {
        void* s = nullptr;
        cudaGetSymbolAddress(&s, g_scratch);
        ctxp = (float*)s;
        wp   = (float*)d_out;
    } else {
        void* s = nullptr;
        cudaGetSymbolAddress(&s, g_scratch);
        ctxp = (float*)d_out;
        wp   = (float*)s;
    }

    static bool attr_done = false;
    if (!attr_done) {
        cudaFuncSetAttribute(attn_mma_kernel,
                             cudaFuncAttributeMaxDynamicSharedMemorySize,
                             SMEM_BYTES);
        attr_done = true;
    }

    split_k_kernel<<<(BH * SEQ * DH / 8 + 255) / 256, 256>>>(k);
    dim3 gt(DH / 32, SEQ / 32, BH), bt(32, 8);
    vt_split_kernel<<<gt, bt>>>(v);

    dim3 ga(SEQ / ROWS, BH), ba(NTHREADS);
    attn_mma_kernel<<<ga, ba, SMEM_BYTES>>>(q, pad, ctxp, wp);
}